// round 8
// baseline (speedup 1.0000x reference)
#include <cuda_runtime.h>
#include <math.h>

#define BB 8
#define TT 1024
#define DD 1024
#define HH 16
#define AD 64
#define BT (BB*TT)      /* 8192 */
#define HA (HH*AD)      /* 1024 */
#define NEDGE 262144
#define BIASDIM 32
#define FBIG 3.402823466e+38f

typedef unsigned long long ull;

// ---------------- scratch (no allocations allowed) ----------------
__device__ float g_q[BT*HA];
__device__ float g_k[BT*HA];
__device__ float g_v[BT*HA];
__device__ float g_ctx[BT*HA];
__device__ float g_ksumT[BB*HH*TT];     // [b][h][t]
__device__ float g_bs[BB*TT*TT];
__device__ int   g_winner[BB*TT*TT];
__device__ float g_alpha[(size_t)BB*HH*TT*TT];
__device__ float g_proj[BIASDIM];
__device__ int   g_is64;

// ---------------- packed f32x2 helpers (sm_103a FFMA2) ----------------
__device__ __forceinline__ ull pk2(float x, float y) {
    ull d; asm("mov.b64 %0, {%1, %2};" : "=l"(d) : "f"(x), "f"(y)); return d;
}
__device__ __forceinline__ ull splat2(float x) {
    ull d; asm("mov.b64 %0, {%1, %1};" : "=l"(d) : "f"(x)); return d;
}
__device__ __forceinline__ ull ffma2(ull a, ull b, ull c) {
    ull d; asm("fma.rn.f32x2 %0, %1, %2, %3;" : "=l"(d) : "l"(a), "l"(b), "l"(c)); return d;
}
__device__ __forceinline__ float2 upk(ull v) {
    float2 r; asm("mov.b64 {%0, %1}, %2;" : "=f"(r.x), "=f"(r.y) : "l"(v)); return r;
}

// ---------------- fast exp (FMA-only, for x <= 0) ----------------
__device__ __forceinline__ float fexp(float x) {
    float y = fmaxf(x * 1.4426950408889634f, -126.0f);
    int   i = __float2int_rn(y);
    float f = y - (float)i;
    float p = 1.5403530e-4f;
    p = fmaf(p, f, 1.3333558e-3f);
    p = fmaf(p, f, 9.6181291e-3f);
    p = fmaf(p, f, 5.5504109e-2f);
    p = fmaf(p, f, 2.4022651e-1f);
    p = fmaf(p, f, 6.9314718e-1f);
    p = fmaf(p, f, 1.0f);
    return p * __int_as_float((i + 127) << 23);
}

// ---------------- dtype detector for attention_bias ----------------
__global__ void detect_kernel(const int* __restrict__ ab32) {
    int ok = 1;
    #pragma unroll
    for (int i = 0; i < 64; i++) ok &= (ab32[2 * i + 1] == 0);
    g_is64 = ok;
}

// ---------------- proj[et] = bias_embs[et] . bias_scalar ----------------
__global__ void proj_kernel(const float* __restrict__ embs, const float* __restrict__ scal) {
    int et = threadIdx.x;
    if (et >= BIASDIM) return;
    float s = 0.f;
    #pragma unroll
    for (int a = 0; a < AD; a++) s += embs[et * AD + a] * scal[a];
    g_proj[et] = s;
}

// ---------------- SGEMM v2: 128x128 tile, BK=16, 8x8 micro, f32x2 ----------------
// which_a: 0=ext A, 1=g_ctx.  which_c: 0=g_q, 1=g_k, 2=g_v, 3=ext C.
__global__ __launch_bounds__(256, 2)
void sgemm2_kernel(const float* __restrict__ Aext, const float* __restrict__ Bm,
                   float* __restrict__ Cext, int which_a, int which_c,
                   int M, int N, int K) {
    const float* A = (which_a == 1) ? g_ctx : Aext;
    float* C = (which_c == 0) ? g_q : (which_c == 1) ? g_k : (which_c == 2) ? g_v : Cext;
    __shared__ float As[16][132];   // [kk][m]
    __shared__ float Bs[16][128];   // [kk][n]
    const int tid = threadIdx.x, tx = tid & 15, ty = tid >> 4;
    const int m0 = blockIdx.y * 128, n0 = blockIdx.x * 128;
    ull acc[8][4];
    #pragma unroll
    for (int i = 0; i < 8; i++)
        #pragma unroll
        for (int j = 0; j < 4; j++) acc[i][j] = 0ull;

    for (int k0 = 0; k0 < K; k0 += 16) {
        #pragma unroll
        for (int i = 0; i < 8; i++) {
            int idx = tid + i * 256;          // 0..2047
            int m = idx >> 4, ka = idx & 15;
            As[ka][m] = A[(size_t)(m0 + m) * K + k0 + ka];
            int n = idx & 127, kb = idx >> 7;
            Bs[kb][n] = Bm[(size_t)(k0 + kb) * N + n0 + n];
        }
        __syncthreads();
        #pragma unroll
        for (int kk = 0; kk < 16; kk++) {
            float4 a0 = *(const float4*)&As[kk][ty * 4];
            float4 a1 = *(const float4*)&As[kk][64 + ty * 4];
            float4 b0 = *(const float4*)&Bs[kk][tx * 4];
            float4 b1 = *(const float4*)&Bs[kk][64 + tx * 4];
            ull bp[4] = { pk2(b0.x, b0.y), pk2(b0.z, b0.w),
                          pk2(b1.x, b1.y), pk2(b1.z, b1.w) };
            float av[8] = { a0.x, a0.y, a0.z, a0.w, a1.x, a1.y, a1.z, a1.w };
            #pragma unroll
            for (int mi = 0; mi < 8; mi++) {
                ull as2 = splat2(av[mi]);
                #pragma unroll
                for (int np = 0; np < 4; np++)
                    acc[mi][np] = ffma2(as2, bp[np], acc[mi][np]);
            }
        }
        __syncthreads();
    }
    #pragma unroll
    for (int ib = 0; ib < 2; ib++)
        #pragma unroll
        for (int i = 0; i < 4; i++) {
            int mi = ib * 4 + i;
            size_t row = (size_t)(m0 + ty * 4 + i + 64 * ib) * N;
            float2 l0 = upk(acc[mi][0]), l1 = upk(acc[mi][1]);
            float2 l2 = upk(acc[mi][2]), l3 = upk(acc[mi][3]);
            *(float4*)&C[row + n0 + tx * 4]      = make_float4(l0.x, l0.y, l1.x, l1.y);
            *(float4*)&C[row + n0 + 64 + tx * 4] = make_float4(l2.x, l2.y, l3.x, l3.y);
        }
}

// ---------------- ksumT[b][h][t] = sum_a k[b,t,h,a] ----------------
__global__ void ksum_kernel() {
    int idx = blockIdx.x * blockDim.x + threadIdx.x;   // bt*H + h
    if (idx >= BT * HH) return;
    int bt = idx / HH, h = idx % HH;
    const float4* p = reinterpret_cast<const float4*>(&g_k[(size_t)bt * HA + h * AD]);
    float s = 0.f;
    #pragma unroll
    for (int i = 0; i < AD / 4; i++) { float4 v4 = p[i]; s += v4.x + v4.y + v4.z + v4.w; }
    int b = bt / TT, t = bt % TT;
    g_ksumT[((size_t)b * HH + h) * TT + t] = s;
}

// ---------------- zero dense bias + winner scratch (vectorized) ----------------
__global__ void zero_bs_kernel() {
    int i = blockIdx.x * blockDim.x + threadIdx.x;
    if (i < BB * TT * TT / 4) {
        ((float4*)g_bs)[i] = make_float4(0.f, 0.f, 0.f, 0.f);
        ((int4*)g_winner)[i] = make_int4(-1, -1, -1, -1);
    }
}

// ---------------- decode edge e ----------------
__device__ __forceinline__ bool decode_edge(const int* __restrict__ ab32, int e,
                                            int& et, int& b, int& qi, int& ki) {
    if (g_is64) {
        const long long* ab = (const long long*)ab32;
        et = (int)ab[4 * e + 0]; b  = (int)ab[4 * e + 1];
        qi = (int)ab[4 * e + 2]; ki = (int)ab[4 * e + 3];
    } else {
        et = ab32[4 * e + 0]; b  = ab32[4 * e + 1];
        qi = ab32[4 * e + 2]; ki = ab32[4 * e + 3];
    }
    return !((unsigned)et >= BIASDIM || (unsigned)b >= BB ||
             (unsigned)qi >= TT || (unsigned)ki >= TT);
}

__global__ void scatter_pass1_kernel(const int* __restrict__ ab32) {
    int e = blockIdx.x * blockDim.x + threadIdx.x;
    if (e >= NEDGE) return;
    int et, b, qi, ki;
    if (!decode_edge(ab32, e, et, b, qi, ki)) return;
    atomicMax(&g_winner[((size_t)b * TT + qi) * TT + ki], e);
}

__global__ void scatter_pass2_kernel(const int* __restrict__ ab32) {
    int e = blockIdx.x * blockDim.x + threadIdx.x;
    if (e >= NEDGE) return;
    int et, b, qi, ki;
    if (!decode_edge(ab32, e, et, b, qi, ki)) return;
    size_t slot = ((size_t)b * TT + qi) * TT + ki;
    if (g_winner[slot] == e) g_bs[slot] = g_proj[et];
}

// ---------------- scores v2: 128x128 tile over (q,k), f32x2 inner ----------------
__global__ __launch_bounds__(256, 2)
void scores2_kernel(const float* __restrict__ masks) {
    __shared__ float Qs[16][132];   // [a-chunk][q]
    __shared__ float Ks[16][132];   // [a-chunk][k]
    const int z = blockIdx.z;                 // b*H + h
    const int b = z >> 4, h = z & 15;
    const int q0 = blockIdx.y * 128, k0c = blockIdx.x * 128;
    const int tid = threadIdx.x, tx = tid & 15, ty = tid >> 4;
    const float* qbase = g_q + (size_t)(b * TT + q0)  * HA + h * AD;
    const float* kbase = g_k + (size_t)(b * TT + k0c) * HA + h * AD;
    ull acc[8][4];
    #pragma unroll
    for (int i = 0; i < 8; i++)
        #pragma unroll
        for (int j = 0; j < 4; j++) acc[i][j] = 0ull;

    for (int a0 = 0; a0 < AD; a0 += 16) {
        #pragma unroll
        for (int i = 0; i < 8; i++) {
            int idx = tid + i * 256;          // 0..2047
            int t = idx >> 4, ka = idx & 15;
            Qs[ka][t] = qbase[(size_t)t * HA + a0 + ka];
            Ks[ka][t] = kbase[(size_t)t * HA + a0 + ka];
        }
        __syncthreads();
        #pragma unroll
        for (int kk = 0; kk < 16; kk++) {
            float4 a0v = *(const float4*)&Qs[kk][ty * 4];
            float4 a1v = *(const float4*)&Qs[kk][64 + ty * 4];
            float4 b0v = *(const float4*)&Ks[kk][tx * 4];
            float4 b1v = *(const float4*)&Ks[kk][64 + tx * 4];
            ull bp[4] = { pk2(b0v.x, b0v.y), pk2(b0v.z, b0v.w),
                          pk2(b1v.x, b1v.y), pk2(b1v.z, b1v.w) };
            float av[8] = { a0v.x, a0v.y, a0v.z, a0v.w, a1v.x, a1v.y, a1v.z, a1v.w };
            #pragma unroll
            for (int mi = 0; mi < 8; mi++) {
                ull as2 = splat2(av[mi]);
                #pragma unroll
                for (int np = 0; np < 4; np++)
                    acc[mi][np] = ffma2(as2, bp[np], acc[mi][np]);
            }
        }
        __syncthreads();
    }
    const float* ksrow = &g_ksumT[((size_t)b * HH + h) * TT];
    #pragma unroll
    for (int ib = 0; ib < 2; ib++)
        #pragma unroll
        for (int i = 0; i < 4; i++) {
            int mi = ib * 4 + i;
            int qg = q0 + ty * 4 + i + 64 * ib;
            size_t rowbm = ((size_t)b * TT + qg) * TT;
            size_t rowal = ((size_t)z * TT + qg) * TT;
            #pragma unroll
            for (int jb = 0; jb < 2; jb++) {
                int kc = k0c + tx * 4 + 64 * jb;
                float4 bs4 = *(const float4*)&g_bs[rowbm + kc];
                float4 mk4 = *(const float4*)&masks[rowbm + kc];
                float4 ks4 = *(const float4*)&ksrow[kc];
                float2 p0 = upk(acc[mi][jb * 2]), p1 = upk(acc[mi][jb * 2 + 1]);
                float4 r;
                r.x = (p0.x + bs4.x * ks4.x) * 0.125f - mk4.x * FBIG;
                r.y = (p0.y + bs4.y * ks4.y) * 0.125f - mk4.y * FBIG;
                r.z = (p1.x + bs4.z * ks4.z) * 0.125f - mk4.z * FBIG;
                r.w = (p1.y + bs4.w * ks4.w) * 0.125f - mk4.w * FBIG;
                *(float4*)&g_alpha[rowal + kc] = r;
            }
        }
}

// ---------------- softmax v2: float4 + fast exp, one block per row ----------------
__global__ void softmax2_kernel() {
    __shared__ float smax[8];
    __shared__ float ssum[8];
    float4* p = (float4*)(g_alpha + (size_t)blockIdx.x * TT);
    const int tid = threadIdx.x;                 // 256
    const int lane = tid & 31, wid = tid >> 5;
    float4 x = p[tid];
    float mx = fmaxf(fmaxf(x.x, x.y), fmaxf(x.z, x.w));
    #pragma unroll
    for (int o = 16; o; o >>= 1) mx = fmaxf(mx, __shfl_xor_sync(0xffffffffu, mx, o));
    if (lane == 0) smax[wid] = mx;
    __syncthreads();
    mx = smax[0];
    #pragma unroll
    for (int w = 1; w < 8; w++) mx = fmaxf(mx, smax[w]);
    x.x = fexp(x.x - mx); x.y = fexp(x.y - mx);
    x.z = fexp(x.z - mx); x.w = fexp(x.w - mx);
    float s = x.x + x.y + x.z + x.w;
    #pragma unroll
    for (int o = 16; o; o >>= 1) s += __shfl_xor_sync(0xffffffffu, s, o);
    if (lane == 0) ssum[wid] = s;
    __syncthreads();
    float tot = 0.f;
    #pragma unroll
    for (int w = 0; w < 8; w++) tot += ssum[w];
    float inv = 1.0f / tot;
    x.x *= inv; x.y *= inv; x.z *= inv; x.w *= inv;
    p[tid] = x;
}

// ---------------- context v2: 128q x 64a tile, f32x2 inner ----------------
__global__ __launch_bounds__(256, 2)
void context2_kernel() {
    __shared__ float Ps[16][132];   // [kk][q]
    __shared__ float Vs[16][64];    // [kk][a]
    const int z = blockIdx.y;                 // b*H + h
    const int b = z >> 4, h = z & 15;
    const int q0 = blockIdx.x * 128;
    const int tid = threadIdx.x, tx = tid & 15, ty = tid >> 4;
    const float* arow  = g_alpha + ((size_t)z * TT + q0) * TT;
    const float* vbase = g_v + (size_t)(b * TT) * HA + h * AD;
    ull acc[8][2];
    #pragma unroll
    for (int i = 0; i < 8; i++) { acc[i][0] = 0ull; acc[i][1] = 0ull; }

    for (int k0 = 0; k0 < TT; k0 += 16) {
        #pragma unroll
        for (int i = 0; i < 8; i++) {
            int idx = tid + i * 256;          // 0..2047
            int m = idx >> 4, ka = idx & 15;
            Ps[ka][m] = arow[(size_t)m * TT + k0 + ka];
        }
        #pragma unroll
        for (int i = 0; i < 4; i++) {
            int idx = tid + i * 256;          // 0..1023
            int a = idx & 63, kb = idx >> 6;
            Vs[kb][a] = vbase[(size_t)(k0 + kb) * HA + a];
        }
        __syncthreads();
        #pragma unroll
        for (int kk = 0; kk < 16; kk++) {
            float4 a0v = *(const float4*)&Ps[kk][ty * 4];
            float4 a1v = *(const float4*)&Ps[kk][64 + ty * 4];
            float4 bv  = *(const float4*)&Vs[kk][tx * 4];
            ull bp[2] = { pk2(bv.x, bv.y), pk2(bv.z, bv.w) };
            float av[8] = { a0v.x, a0v.y, a0v.z, a0v.w, a1v.x, a1v.y, a1v.z, a1v.w };
            #pragma unroll
            for (int mi = 0; mi < 8; mi++) {
                ull as2 = splat2(av[mi]);
                acc[mi][0] = ffma2(as2, bp[0], acc[mi][0]);
                acc[mi][1] = ffma2(as2, bp[1], acc[mi][1]);
            }
        }
        __syncthreads();
    }
    #pragma unroll
    for (int ib = 0; ib < 2; ib++)
        #pragma unroll
        for (int i = 0; i < 4; i++) {
            int mi = ib * 4 + i;
            int qg = q0 + ty * 4 + i + 64 * ib;
            float2 l0 = upk(acc[mi][0]), l1 = upk(acc[mi][1]);
            *(float4*)&g_ctx[(size_t)(b * TT + qg) * HA + h * AD + tx * 4] =
                make_float4(l0.x, l0.y, l1.x, l1.y);
        }
}

// ---------------- launch ----------------
extern "C" void kernel_launch(void* const* d_in, const int* in_sizes, int n_in,
                              void* d_out, int out_size) {
    const float* states     = (const float*)d_in[0];
    const float* key_states = (const float*)d_in[1];
    const float* masks      = (const float*)d_in[2];
    const int*   ab32       = (const int*)d_in[3];
    const float* Wq         = (const float*)d_in[4];
    const float* Wk         = (const float*)d_in[5];
    const float* Wv         = (const float*)d_in[6];
    const float* Wout       = (const float*)d_in[7];
    const float* embs       = (const float*)d_in[8];
    const float* scal       = (const float*)d_in[9];
    float* out              = (float*)d_out;

    dim3 gemm_grid(HA / 128, BT / 128);   // (8, 64)

    // QKV projections
    sgemm2_kernel<<<gemm_grid, 256>>>(states,     Wq, nullptr, 0, 0, BT, HA, DD);
    sgemm2_kernel<<<gemm_grid, 256>>>(key_states, Wk, nullptr, 0, 1, BT, HA, DD);
    sgemm2_kernel<<<gemm_grid, 256>>>(key_states, Wv, nullptr, 0, 2, BT, HA, DD);

    // ksum (transposed layout)
    ksum_kernel<<<(BT * HH + 255) / 256, 256>>>();

    // edge-bias detect + projection + deterministic scatter
    detect_kernel<<<1, 1>>>(ab32);
    proj_kernel<<<1, 32>>>(embs, scal);
    zero_bs_kernel<<<(BB * TT * TT / 4 + 255) / 256, 256>>>();
    scatter_pass1_kernel<<<(NEDGE + 255) / 256, 256>>>(ab32);
    scatter_pass2_kernel<<<(NEDGE + 255) / 256, 256>>>(ab32);

    // scores + softmax
    dim3 sc_grid(TT / 128, TT / 128, BB * HH);   // (8, 8, 128)
    scores2_kernel<<<sc_grid, 256>>>(masks);
    softmax2_kernel<<<BB * HH * TT, 256>>>();

    // context
    dim3 cx_grid(TT / 128, BB * HH);             // (8, 128)
    context2_kernel<<<cx_grid, 256>>>();

    // output projection
    sgemm2_kernel<<<gemm_grid, 256>>>(nullptr, Wout, out, 1, 3, BT, DD, HA);
}

// round 9
// speedup vs baseline: 1.4613x; 1.4613x over previous
#include <cuda_runtime.h>
#include <math.h>

#define BB 8
#define TT 1024
#define DD 1024
#define HH 16
#define AD 64
#define BT (BB*TT)      /* 8192 */
#define HA (HH*AD)      /* 1024 */
#define NEDGE 262144
#define BIASDIM 32
#define FBIG 3.402823466e+38f

// ---------------- scratch (no allocations allowed) ----------------
__device__ float g_q[BT*HA];
__device__ float g_k[BT*HA];
__device__ float g_v[BT*HA];
__device__ float g_ctx[BT*HA];
__device__ float g_ksum[BT*HH];        // [bt][h]
__device__ float g_bs[BB*TT*TT];
__device__ int   g_winner[BB*TT*TT];
__device__ float g_alpha[(size_t)BB*HH*TT*TT];
__device__ float g_proj[BIASDIM];
__device__ int   g_is64;

// ---------------- tf32 helpers ----------------
__device__ __forceinline__ unsigned cvt_tf32(float x) {
    unsigned r; asm("cvt.rna.tf32.f32 %0, %1;" : "=r"(r) : "f"(x)); return r;
}
__device__ __forceinline__ void mma_tf32(float (&d)[4], const unsigned (&a)[4],
                                         const unsigned (&b)[2]) {
    asm("mma.sync.aligned.m16n8k8.row.col.f32.tf32.tf32.f32 "
        "{%0,%1,%2,%3}, {%4,%5,%6,%7}, {%8,%9}, {%0,%1,%2,%3};"
        : "+f"(d[0]), "+f"(d[1]), "+f"(d[2]), "+f"(d[3])
        : "r"(a[0]), "r"(a[1]), "r"(a[2]), "r"(a[3]), "r"(b[0]), "r"(b[1]));
}

// ---------------- fast exp (FMA-only, for x <= 0) ----------------
__device__ __forceinline__ float fexp(float x) {
    float y = fmaxf(x * 1.4426950408889634f, -126.0f);
    int   i = __float2int_rn(y);
    float f = y - (float)i;
    float p = 1.5403530e-4f;
    p = fmaf(p, f, 1.3333558e-3f);
    p = fmaf(p, f, 9.6181291e-3f);
    p = fmaf(p, f, 5.5504109e-2f);
    p = fmaf(p, f, 2.4022651e-1f);
    p = fmaf(p, f, 6.9314718e-1f);
    p = fmaf(p, f, 1.0f);
    return p * __int_as_float((i + 127) << 23);
}

// ---------------- dtype detector for attention_bias ----------------
__global__ void detect_kernel(const int* __restrict__ ab32) {
    int ok = 1;
    #pragma unroll
    for (int i = 0; i < 64; i++) ok &= (ab32[2 * i + 1] == 0);
    g_is64 = ok;
}

// ---------------- proj[et] = bias_embs[et] . bias_scalar ----------------
__global__ void proj_kernel(const float* __restrict__ embs, const float* __restrict__ scal) {
    int et = threadIdx.x;
    if (et >= BIASDIM) return;
    float s = 0.f;
    #pragma unroll
    for (int a = 0; a < AD; a++) s += embs[et * AD + a] * scal[a];
    g_proj[et] = s;
}

// ---------------- TF32 tensor-core GEMM: C[M,N] = A[M,K] @ B[K,N] ----------------
// 3xTF32: split each operand into hi (tf32-rounded) + lo (residual, tf32-rounded);
// accumulate Ahi*Bhi + Ahi*Blo + Alo*Bhi in fp32 -> near-fp32 accuracy.
// Tile 128x128, BK=16, 256 threads = 8 warps in 4(m) x 2(n); warp tile 32x64.
// which_a: 0=ext A, 1=g_ctx.  which_c: 0=g_q, 1=g_k, 2=g_v, 3=ext C.
__global__ __launch_bounds__(256, 2)
void tf32_gemm_kernel(const float* __restrict__ Aext, const float* __restrict__ Bm,
                      float* __restrict__ Cext, int which_a, int which_c,
                      int M, int N, int K) {
    const float* A = (which_a == 1) ? g_ctx : Aext;
    float* C = (which_c == 0) ? g_q : (which_c == 1) ? g_k : (which_c == 2) ? g_v : Cext;
    __shared__ unsigned Ah[16][136], Al[16][136];   // [k][m], pad->row stride mod32 = 8
    __shared__ unsigned Bh[16][136], Bl[16][136];   // [k][n]
    const int tid = threadIdx.x;
    const int wid = tid >> 5, lane = tid & 31;
    const int quad = lane >> 2, tq = lane & 3;
    const int warp_m = wid >> 1, warp_n = wid & 1;
    const int m0 = blockIdx.y * 128, n0 = blockIdx.x * 128;

    float acc[2][8][4];
    #pragma unroll
    for (int mf = 0; mf < 2; mf++)
        #pragma unroll
        for (int nf = 0; nf < 8; nf++)
            #pragma unroll
            for (int r = 0; r < 4; r++) acc[mf][nf][r] = 0.f;

    for (int k0 = 0; k0 < K; k0 += 16) {
        // stage A tile 128x16 (row-major in gmem) -> Ah/Al[k][m]
        #pragma unroll
        for (int it = 0; it < 2; it++) {
            int idx = tid + it * 256;           // 0..511
            int row = idx >> 2, kg = (idx & 3) * 4;
            float4 v = *(const float4*)&A[(size_t)(m0 + row) * K + k0 + kg];
            float vv[4] = { v.x, v.y, v.z, v.w };
            #pragma unroll
            for (int j = 0; j < 4; j++) {
                unsigned h = cvt_tf32(vv[j]);
                float lo = vv[j] - __uint_as_float(h);
                Ah[kg + j][row] = h;
                Al[kg + j][row] = cvt_tf32(lo);
            }
        }
        // stage B tile 16x128 -> Bh/Bl[k][n]
        #pragma unroll
        for (int it = 0; it < 2; it++) {
            int idx = tid + it * 256;           // 0..511
            int row = idx >> 5, ng = (idx & 31) * 4;
            float4 v = *(const float4*)&Bm[(size_t)(k0 + row) * N + n0 + ng];
            uint4 h, l;
            h.x = cvt_tf32(v.x); l.x = cvt_tf32(v.x - __uint_as_float(h.x));
            h.y = cvt_tf32(v.y); l.y = cvt_tf32(v.y - __uint_as_float(h.y));
            h.z = cvt_tf32(v.z); l.z = cvt_tf32(v.z - __uint_as_float(h.z));
            h.w = cvt_tf32(v.w); l.w = cvt_tf32(v.w - __uint_as_float(h.w));
            *(uint4*)&Bh[row][ng] = h;
            *(uint4*)&Bl[row][ng] = l;
        }
        __syncthreads();

        #pragma unroll
        for (int ks = 0; ks < 16; ks += 8) {
            unsigned afh[2][4], afl[2][4];
            #pragma unroll
            for (int mf = 0; mf < 2; mf++) {
                int mr = warp_m * 32 + mf * 16 + quad;
                afh[mf][0] = Ah[ks + tq][mr];     afh[mf][1] = Ah[ks + tq][mr + 8];
                afh[mf][2] = Ah[ks + tq + 4][mr]; afh[mf][3] = Ah[ks + tq + 4][mr + 8];
                afl[mf][0] = Al[ks + tq][mr];     afl[mf][1] = Al[ks + tq][mr + 8];
                afl[mf][2] = Al[ks + tq + 4][mr]; afl[mf][3] = Al[ks + tq + 4][mr + 8];
            }
            #pragma unroll
            for (int nf = 0; nf < 8; nf++) {
                int nc = warp_n * 64 + nf * 8 + quad;
                unsigned bh[2] = { Bh[ks + tq][nc], Bh[ks + tq + 4][nc] };
                unsigned bl[2] = { Bl[ks + tq][nc], Bl[ks + tq + 4][nc] };
                #pragma unroll
                for (int mf = 0; mf < 2; mf++) {
                    mma_tf32(acc[mf][nf], afh[mf], bh);
                    mma_tf32(acc[mf][nf], afh[mf], bl);
                    mma_tf32(acc[mf][nf], afl[mf], bh);
                }
            }
        }
        __syncthreads();
    }

    // epilogue
    #pragma unroll
    for (int mf = 0; mf < 2; mf++) {
        int row0 = m0 + warp_m * 32 + mf * 16 + quad;
        #pragma unroll
        for (int nf = 0; nf < 8; nf++) {
            int col = n0 + warp_n * 64 + nf * 8 + 2 * tq;
            *(float2*)&C[(size_t)row0 * N + col] =
                make_float2(acc[mf][nf][0], acc[mf][nf][1]);
            *(float2*)&C[(size_t)(row0 + 8) * N + col] =
                make_float2(acc[mf][nf][2], acc[mf][nf][3]);
        }
    }
}

// ---------------- ksum[bt][h] = sum_a k[b,t,h,a] ----------------
__global__ void ksum_kernel() {
    int idx = blockIdx.x * blockDim.x + threadIdx.x;   // bt*H + h
    if (idx >= BT * HH) return;
    int bt = idx / HH, h = idx % HH;
    const float4* p = reinterpret_cast<const float4*>(&g_k[(size_t)bt * HA + h * AD]);
    float s = 0.f;
    #pragma unroll
    for (int i = 0; i < AD / 4; i++) { float4 v4 = p[i]; s += v4.x + v4.y + v4.z + v4.w; }
    g_ksum[idx] = s;
}

// ---------------- zero dense bias + winner scratch ----------------
__global__ void zero_bs_kernel() {
    int i = blockIdx.x * blockDim.x + threadIdx.x;
    if (i < BB * TT * TT / 4) {
        ((float4*)g_bs)[i] = make_float4(0.f, 0.f, 0.f, 0.f);
        ((int4*)g_winner)[i] = make_int4(-1, -1, -1, -1);
    }
}

// ---------------- decode edge e ----------------
__device__ __forceinline__ bool decode_edge(const int* __restrict__ ab32, int e,
                                            int& et, int& b, int& qi, int& ki) {
    if (g_is64) {
        const long long* ab = (const long long*)ab32;
        et = (int)ab[4 * e + 0]; b  = (int)ab[4 * e + 1];
        qi = (int)ab[4 * e + 2]; ki = (int)ab[4 * e + 3];
    } else {
        et = ab32[4 * e + 0]; b  = ab32[4 * e + 1];
        qi = ab32[4 * e + 2]; ki = ab32[4 * e + 3];
    }
    return !((unsigned)et >= BIASDIM || (unsigned)b >= BB ||
             (unsigned)qi >= TT || (unsigned)ki >= TT);
}

__global__ void scatter_pass1_kernel(const int* __restrict__ ab32) {
    int e = blockIdx.x * blockDim.x + threadIdx.x;
    if (e >= NEDGE) return;
    int et, b, qi, ki;
    if (!decode_edge(ab32, e, et, b, qi, ki)) return;
    atomicMax(&g_winner[((size_t)b * TT + qi) * TT + ki], e);
}

__global__ void scatter_pass2_kernel(const int* __restrict__ ab32) {
    int e = blockIdx.x * blockDim.x + threadIdx.x;
    if (e >= NEDGE) return;
    int et, b, qi, ki;
    if (!decode_edge(ab32, e, et, b, qi, ki)) return;
    size_t slot = ((size_t)b * TT + qi) * TT + ki;
    if (g_winner[slot] == e) g_bs[slot] = g_proj[et];
}

// ---------------- scores: alpha[b,h,q,k] = (q.k + bs*ksum)*0.125 - mask*BIG ----------------
__global__ void scores_kernel(const float* __restrict__ masks) {
    __shared__ float Qs[64][65];   // [a][q]
    __shared__ float Ks[64][65];   // [a][k]
    const int z = blockIdx.z;                 // b*H + h
    const int b = z >> 4, h = z & 15;
    const int q0 = blockIdx.y * 64, k0 = blockIdx.x * 64;
    const int tid = threadIdx.x, tx = tid & 15, ty = tid >> 4;
    const float* qbase = g_q + (size_t)(b * TT + q0) * HA + h * AD;
    const float* kbase = g_k + (size_t)(b * TT + k0) * HA + h * AD;
    #pragma unroll
    for (int i = 0; i < 16; i++) {
        int idx = tid + i * 256;              // 0..4095
        int t = idx >> 6, a = idx & 63;
        Qs[a][t] = qbase[(size_t)t * HA + a];
        Ks[a][t] = kbase[(size_t)t * HA + a];
    }
    __syncthreads();
    float acc[4][4] = {};
    #pragma unroll
    for (int a = 0; a < 64; a++) {
        float qr[4], kr[4];
        #pragma unroll
        for (int i = 0; i < 4; i++) qr[i] = Qs[a][ty + 16 * i];
        #pragma unroll
        for (int j = 0; j < 4; j++) kr[j] = Ks[a][tx + 16 * j];
        #pragma unroll
        for (int i = 0; i < 4; i++)
            #pragma unroll
            for (int j = 0; j < 4; j++)
                acc[i][j] += qr[i] * kr[j];
    }
    #pragma unroll
    for (int i = 0; i < 4; i++) {
        int qi = q0 + ty + 16 * i;
        #pragma unroll
        for (int j = 0; j < 4; j++) {
            int ki = k0 + tx + 16 * j;
            float bias = g_bs[((size_t)b * TT + qi) * TT + ki] *
                         g_ksum[(size_t)(b * TT + ki) * HH + h];
            float val = (acc[i][j] + bias) * 0.125f;   // 1/sqrt(64)
            val -= masks[((size_t)b * TT + qi) * TT + ki] * FBIG;
            g_alpha[((size_t)z * TT + qi) * TT + ki] = val;
        }
    }
}

// ---------------- softmax: float4 + fast exp, one block per row ----------------
__global__ void softmax_kernel() {
    __shared__ float smax[8];
    __shared__ float ssum[8];
    float4* p = (float4*)(g_alpha + (size_t)blockIdx.x * TT);
    const int tid = threadIdx.x;                 // 256
    const int lane = tid & 31, wid = tid >> 5;
    float4 x = p[tid];
    float mx = fmaxf(fmaxf(x.x, x.y), fmaxf(x.z, x.w));
    #pragma unroll
    for (int o = 16; o; o >>= 1) mx = fmaxf(mx, __shfl_xor_sync(0xffffffffu, mx, o));
    if (lane == 0) smax[wid] = mx;
    __syncthreads();
    mx = smax[0];
    #pragma unroll
    for (int w = 1; w < 8; w++) mx = fmaxf(mx, smax[w]);
    x.x = fexp(x.x - mx); x.y = fexp(x.y - mx);
    x.z = fexp(x.z - mx); x.w = fexp(x.w - mx);
    float s = x.x + x.y + x.z + x.w;
    #pragma unroll
    for (int o = 16; o; o >>= 1) s += __shfl_xor_sync(0xffffffffu, s, o);
    if (lane == 0) ssum[wid] = s;
    __syncthreads();
    float tot = 0.f;
    #pragma unroll
    for (int w = 0; w < 8; w++) tot += ssum[w];
    float inv = 1.0f / tot;
    x.x *= inv; x.y *= inv; x.z *= inv; x.w *= inv;
    p[tid] = x;
}

// ---------------- context: ctx[b,q,h,a] = sum_k alpha[b,h,q,k] * v[b,k,h,a] ----------------
__global__ void context_kernel() {
    __shared__ float Ps[32][65];   // [kk][q]
    __shared__ float Vs[32][65];   // [kk][a]
    const int z = blockIdx.y;                 // b*H + h
    const int b = z >> 4, h = z & 15;
    const int q0 = blockIdx.x * 64;
    const int tid = threadIdx.x, tx = tid & 15, ty = tid >> 4;
    const float* prow  = g_alpha + ((size_t)z * TT + q0) * TT;
    const float* vbase = g_v + (size_t)(b * TT) * HA + h * AD;
    float acc[4][4] = {};
    for (int k0 = 0; k0 < TT; k0 += 32) {
        #pragma unroll
        for (int i = 0; i < 8; i++) {
            int idx = tid + i * 256;          // 0..2047
            int t = idx >> 5, ka = idx & 31;
            Ps[ka][t] = prow[(size_t)t * TT + k0 + ka];
            int a = idx & 63, kb = idx >> 6;  // kb 0..31
            Vs[kb][a] = vbase[(size_t)(k0 + kb) * HA + a];
        }
        __syncthreads();
        #pragma unroll
        for (int kk = 0; kk < 32; kk++) {
            float pr[4], vr[4];
            #pragma unroll
            for (int i = 0; i < 4; i++) pr[i] = Ps[kk][ty + 16 * i];
            #pragma unroll
            for (int j = 0; j < 4; j++) vr[j] = Vs[kk][tx + 16 * j];
            #pragma unroll
            for (int i = 0; i < 4; i++)
                #pragma unroll
                for (int j = 0; j < 4; j++)
                    acc[i][j] += pr[i] * vr[j];
        }
        __syncthreads();
    }
    #pragma unroll
    for (int i = 0; i < 4; i++)
        #pragma unroll
        for (int j = 0; j < 4; j++)
            g_ctx[(size_t)(b * TT + q0 + ty + 16 * i) * HA + h * AD + tx + 16 * j] = acc[i][j];
}

// ---------------- launch ----------------
extern "C" void kernel_launch(void* const* d_in, const int* in_sizes, int n_in,
                              void* d_out, int out_size) {
    const float* states     = (const float*)d_in[0];
    const float* key_states = (const float*)d_in[1];
    const float* masks      = (const float*)d_in[2];
    const int*   ab32       = (const int*)d_in[3];
    const float* Wq         = (const float*)d_in[4];
    const float* Wk         = (const float*)d_in[5];
    const float* Wv         = (const float*)d_in[6];
    const float* Wout       = (const float*)d_in[7];
    const float* embs       = (const float*)d_in[8];
    const float* scal       = (const float*)d_in[9];
    float* out              = (float*)d_out;

    dim3 gemm_grid(HA / 128, BT / 128);   // (8, 64)

    // QKV projections — TF32 tensor cores (3xTF32 for fp32 accuracy)
    tf32_gemm_kernel<<<gemm_grid, 256>>>(states,     Wq, nullptr, 0, 0, BT, HA, DD);
    tf32_gemm_kernel<<<gemm_grid, 256>>>(key_states, Wk, nullptr, 0, 1, BT, HA, DD);
    tf32_gemm_kernel<<<gemm_grid, 256>>>(key_states, Wv, nullptr, 0, 2, BT, HA, DD);

    // ksum
    ksum_kernel<<<(BT * HH + 255) / 256, 256>>>();

    // edge-bias detect + projection + deterministic scatter
    detect_kernel<<<1, 1>>>(ab32);
    proj_kernel<<<1, 32>>>(embs, scal);
    zero_bs_kernel<<<(BB * TT * TT / 4 + 255) / 256, 256>>>();
    scatter_pass1_kernel<<<(NEDGE + 255) / 256, 256>>>(ab32);
    scatter_pass2_kernel<<<(NEDGE + 255) / 256, 256>>>(ab32);

    // scores + softmax
    dim3 sc_grid(TT / 64, TT / 64, BB * HH);   // (16, 16, 128)
    scores_kernel<<<sc_grid, 256>>>(masks);
    softmax_kernel<<<BB * HH * TT, 256>>>();

    // context
    dim3 cx_grid(TT / 64, BB * HH);            // (16, 128)
    context_kernel<<<cx_grid, 256>>>();

    // output projection — TF32 tensor cores
    tf32_gemm_kernel<<<gemm_grid, 256>>>(nullptr, Wout, out, 1, 3, BT, DD, HA);
}

// round 10
// speedup vs baseline: 1.6408x; 1.1229x over previous
#include <cuda_runtime.h>
#include <math.h>

#define BB 8
#define TT 1024
#define DD 1024
#define HH 16
#define AD 64
#define BT (BB*TT)      /* 8192 */
#define HA (HH*AD)      /* 1024 */
#define NEDGE 262144
#define BIASDIM 32
#define FBIG 3.402823466e+38f

// ---------------- scratch (no allocations allowed) ----------------
__device__ float g_q[BT*HA];
__device__ float g_k[BT*HA];
__device__ float g_v[BT*HA];
__device__ float g_ctx[BT*HA];
__device__ float g_ksum[BT*HH];        // [bt][h]
__device__ float g_bs[BB*TT*TT];
__device__ int   g_winner[BB*TT*TT];
__device__ float g_alpha[(size_t)BB*HH*TT*TT];
__device__ float g_proj[BIASDIM];
__device__ int   g_is64;

// ---------------- tf32 helpers ----------------
__device__ __forceinline__ unsigned cvt_tf32(float x) {
    unsigned r; asm("cvt.rna.tf32.f32 %0, %1;" : "=r"(r) : "f"(x)); return r;
}
__device__ __forceinline__ void mma_tf32(float (&d)[4], const unsigned (&a)[4],
                                         const unsigned (&b)[2]) {
    asm("mma.sync.aligned.m16n8k8.row.col.f32.tf32.tf32.f32 "
        "{%0,%1,%2,%3}, {%4,%5,%6,%7}, {%8,%9}, {%0,%1,%2,%3};"
        : "+f"(d[0]), "+f"(d[1]), "+f"(d[2]), "+f"(d[3])
        : "r"(a[0]), "r"(a[1]), "r"(a[2]), "r"(a[3]), "r"(b[0]), "r"(b[1]));
}

// ---------------- fast exp (FMA-only, for x <= 0) ----------------
__device__ __forceinline__ float fexp(float x) {
    float y = fmaxf(x * 1.4426950408889634f, -126.0f);
    int   i = __float2int_rn(y);
    float f = y - (float)i;
    float p = 1.5403530e-4f;
    p = fmaf(p, f, 1.3333558e-3f);
    p = fmaf(p, f, 9.6181291e-3f);
    p = fmaf(p, f, 5.5504109e-2f);
    p = fmaf(p, f, 2.4022651e-1f);
    p = fmaf(p, f, 6.9314718e-1f);
    p = fmaf(p, f, 1.0f);
    return p * __int_as_float((i + 127) << 23);
}

// ---------------- dtype detector for attention_bias ----------------
__global__ void detect_kernel(const int* __restrict__ ab32) {
    int ok = 1;
    #pragma unroll
    for (int i = 0; i < 64; i++) ok &= (ab32[2 * i + 1] == 0);
    g_is64 = ok;
}

// ---------------- proj[et] = bias_embs[et] . bias_scalar ----------------
__global__ void proj_kernel(const float* __restrict__ embs, const float* __restrict__ scal) {
    int et = threadIdx.x;
    if (et >= BIASDIM) return;
    float s = 0.f;
    #pragma unroll
    for (int a = 0; a < AD; a++) s += embs[et * AD + a] * scal[a];
    g_proj[et] = s;
}

// ---------------- TF32 tensor-core GEMM: C[M,N] = A[M,K] @ B[K,N] ----------------
__global__ __launch_bounds__(256, 2)
void tf32_gemm_kernel(const float* __restrict__ Aext, const float* __restrict__ Bm,
                      float* __restrict__ Cext, int which_a, int which_c,
                      int M, int N, int K) {
    const float* A = (which_a == 1) ? g_ctx : Aext;
    float* C = (which_c == 0) ? g_q : (which_c == 1) ? g_k : (which_c == 2) ? g_v : Cext;
    __shared__ unsigned Ah[16][136], Al[16][136];   // [k][m]
    __shared__ unsigned Bh[16][136], Bl[16][136];   // [k][n]
    const int tid = threadIdx.x;
    const int wid = tid >> 5, lane = tid & 31;
    const int g = lane >> 2, tq = lane & 3;
    const int warp_m = wid >> 1, warp_n = wid & 1;
    const int m0 = blockIdx.y * 128, n0 = blockIdx.x * 128;

    float acc[2][8][4];
    #pragma unroll
    for (int mf = 0; mf < 2; mf++)
        #pragma unroll
        for (int nf = 0; nf < 8; nf++)
            #pragma unroll
            for (int r = 0; r < 4; r++) acc[mf][nf][r] = 0.f;

    for (int k0 = 0; k0 < K; k0 += 16) {
        #pragma unroll
        for (int it = 0; it < 2; it++) {
            int idx = tid + it * 256;           // 0..511
            int row = idx >> 2, kg = (idx & 3) * 4;
            float4 v = *(const float4*)&A[(size_t)(m0 + row) * K + k0 + kg];
            float vv[4] = { v.x, v.y, v.z, v.w };
            #pragma unroll
            for (int j = 0; j < 4; j++) {
                unsigned h = cvt_tf32(vv[j]);
                Ah[kg + j][row] = h;
                Al[kg + j][row] = cvt_tf32(vv[j] - __uint_as_float(h));
            }
        }
        #pragma unroll
        for (int it = 0; it < 2; it++) {
            int idx = tid + it * 256;           // 0..511
            int row = idx >> 5, ng = (idx & 31) * 4;
            float4 v = *(const float4*)&Bm[(size_t)(k0 + row) * N + n0 + ng];
            uint4 h, l;
            h.x = cvt_tf32(v.x); l.x = cvt_tf32(v.x - __uint_as_float(h.x));
            h.y = cvt_tf32(v.y); l.y = cvt_tf32(v.y - __uint_as_float(h.y));
            h.z = cvt_tf32(v.z); l.z = cvt_tf32(v.z - __uint_as_float(h.z));
            h.w = cvt_tf32(v.w); l.w = cvt_tf32(v.w - __uint_as_float(h.w));
            *(uint4*)&Bh[row][ng] = h;
            *(uint4*)&Bl[row][ng] = l;
        }
        __syncthreads();

        #pragma unroll
        for (int ks = 0; ks < 16; ks += 8) {
            unsigned afh[2][4], afl[2][4];
            #pragma unroll
            for (int mf = 0; mf < 2; mf++) {
                int mr = warp_m * 32 + mf * 16 + g;
                afh[mf][0] = Ah[ks + tq][mr];     afh[mf][1] = Ah[ks + tq][mr + 8];
                afh[mf][2] = Ah[ks + tq + 4][mr]; afh[mf][3] = Ah[ks + tq + 4][mr + 8];
                afl[mf][0] = Al[ks + tq][mr];     afl[mf][1] = Al[ks + tq][mr + 8];
                afl[mf][2] = Al[ks + tq + 4][mr]; afl[mf][3] = Al[ks + tq + 4][mr + 8];
            }
            #pragma unroll
            for (int nf = 0; nf < 8; nf++) {
                int nc = warp_n * 64 + nf * 8 + g;
                unsigned bh[2] = { Bh[ks + tq][nc], Bh[ks + tq + 4][nc] };
                unsigned bl[2] = { Bl[ks + tq][nc], Bl[ks + tq + 4][nc] };
                #pragma unroll
                for (int mf = 0; mf < 2; mf++) {
                    mma_tf32(acc[mf][nf], afh[mf], bh);
                    mma_tf32(acc[mf][nf], afh[mf], bl);
                    mma_tf32(acc[mf][nf], afl[mf], bh);
                }
            }
        }
        __syncthreads();
    }

    #pragma unroll
    for (int mf = 0; mf < 2; mf++) {
        int row0 = m0 + warp_m * 32 + mf * 16 + g;
        #pragma unroll
        for (int nf = 0; nf < 8; nf++) {
            int col = n0 + warp_n * 64 + nf * 8 + 2 * tq;
            *(float2*)&C[(size_t)row0 * N + col] =
                make_float2(acc[mf][nf][0], acc[mf][nf][1]);
            *(float2*)&C[(size_t)(row0 + 8) * N + col] =
                make_float2(acc[mf][nf][2], acc[mf][nf][3]);
        }
    }
}

// ---------------- ksum[bt][h] = sum_a k[b,t,h,a] ----------------
__global__ void ksum_kernel() {
    int idx = blockIdx.x * blockDim.x + threadIdx.x;   // bt*H + h
    if (idx >= BT * HH) return;
    int bt = idx / HH, h = idx % HH;
    const float4* p = reinterpret_cast<const float4*>(&g_k[(size_t)bt * HA + h * AD]);
    float s = 0.f;
    #pragma unroll
    for (int i = 0; i < AD / 4; i++) { float4 v4 = p[i]; s += v4.x + v4.y + v4.z + v4.w; }
    g_ksum[idx] = s;
}

// ---------------- zero dense bias + winner scratch ----------------
__global__ void zero_bs_kernel() {
    int i = blockIdx.x * blockDim.x + threadIdx.x;
    if (i < BB * TT * TT / 4) {
        ((float4*)g_bs)[i] = make_float4(0.f, 0.f, 0.f, 0.f);
        ((int4*)g_winner)[i] = make_int4(-1, -1, -1, -1);
    }
}

// ---------------- decode edge e ----------------
__device__ __forceinline__ bool decode_edge(const int* __restrict__ ab32, int e,
                                            int& et, int& b, int& qi, int& ki) {
    if (g_is64) {
        const long long* ab = (const long long*)ab32;
        et = (int)ab[4 * e + 0]; b  = (int)ab[4 * e + 1];
        qi = (int)ab[4 * e + 2]; ki = (int)ab[4 * e + 3];
    } else {
        et = ab32[4 * e + 0]; b  = ab32[4 * e + 1];
        qi = ab32[4 * e + 2]; ki = ab32[4 * e + 3];
    }
    return !((unsigned)et >= BIASDIM || (unsigned)b >= BB ||
             (unsigned)qi >= TT || (unsigned)ki >= TT);
}

__global__ void scatter_pass1_kernel(const int* __restrict__ ab32) {
    int e = blockIdx.x * blockDim.x + threadIdx.x;
    if (e >= NEDGE) return;
    int et, b, qi, ki;
    if (!decode_edge(ab32, e, et, b, qi, ki)) return;
    atomicMax(&g_winner[((size_t)b * TT + qi) * TT + ki], e);
}

__global__ void scatter_pass2_kernel(const int* __restrict__ ab32) {
    int e = blockIdx.x * blockDim.x + threadIdx.x;
    if (e >= NEDGE) return;
    int et, b, qi, ki;
    if (!decode_edge(ab32, e, et, b, qi, ki)) return;
    size_t slot = ((size_t)b * TT + qi) * TT + ki;
    if (g_winner[slot] == e) g_bs[slot] = g_proj[et];
}

// ---------------- scores TF32: alpha = (QK^T + bs*ksum)*0.125 - mask*BIG ----------
// Per (b,h): C[q,k] = sum_a Q[q,a] * K[k,a].  Both operands a-contiguous ->
// staged identically ([a][t] smem), row.col mma.  128x128 tile, K-dim 64.
__global__ __launch_bounds__(256, 2)
void scores_tf32_kernel(const float* __restrict__ masks) {
    __shared__ unsigned Ah[16][136], Al[16][136];   // Q: [a][q]
    __shared__ unsigned Bh[16][136], Bl[16][136];   // K: [a][k]
    __shared__ float ks_s[128];
    const int z = blockIdx.z;                 // b*H + h
    const int b = z >> 4, h = z & 15;
    const int q0 = blockIdx.y * 128, k0c = blockIdx.x * 128;
    const int tid = threadIdx.x;
    const int wid = tid >> 5, lane = tid & 31;
    const int g = lane >> 2, tq = lane & 3;
    const int warp_m = wid >> 1, warp_n = wid & 1;
    const float* qbase = g_q + (size_t)(b * TT + q0)  * HA + h * AD;
    const float* kbase = g_k + (size_t)(b * TT + k0c) * HA + h * AD;
    if (tid < 128) ks_s[tid] = g_ksum[(size_t)(b * TT + k0c + tid) * HH + h];

    float acc[2][8][4];
    #pragma unroll
    for (int mf = 0; mf < 2; mf++)
        #pragma unroll
        for (int nf = 0; nf < 8; nf++)
            #pragma unroll
            for (int r = 0; r < 4; r++) acc[mf][nf][r] = 0.f;

    for (int a0 = 0; a0 < AD; a0 += 16) {
        #pragma unroll
        for (int it = 0; it < 2; it++) {
            int idx = tid + it * 256;           // 0..511
            int row = idx >> 2, kg = (idx & 3) * 4;
            float4 v = *(const float4*)&qbase[(size_t)row * HA + a0 + kg];
            float4 w = *(const float4*)&kbase[(size_t)row * HA + a0 + kg];
            float vv[4] = { v.x, v.y, v.z, v.w };
            float ww[4] = { w.x, w.y, w.z, w.w };
            #pragma unroll
            for (int j = 0; j < 4; j++) {
                unsigned hq = cvt_tf32(vv[j]);
                Ah[kg + j][row] = hq;
                Al[kg + j][row] = cvt_tf32(vv[j] - __uint_as_float(hq));
                unsigned hk = cvt_tf32(ww[j]);
                Bh[kg + j][row] = hk;
                Bl[kg + j][row] = cvt_tf32(ww[j] - __uint_as_float(hk));
            }
        }
        __syncthreads();
        #pragma unroll
        for (int ks = 0; ks < 16; ks += 8) {
            unsigned afh[2][4], afl[2][4];
            #pragma unroll
            for (int mf = 0; mf < 2; mf++) {
                int mr = warp_m * 32 + mf * 16 + g;
                afh[mf][0] = Ah[ks + tq][mr];     afh[mf][1] = Ah[ks + tq][mr + 8];
                afh[mf][2] = Ah[ks + tq + 4][mr]; afh[mf][3] = Ah[ks + tq + 4][mr + 8];
                afl[mf][0] = Al[ks + tq][mr];     afl[mf][1] = Al[ks + tq][mr + 8];
                afl[mf][2] = Al[ks + tq + 4][mr]; afl[mf][3] = Al[ks + tq + 4][mr + 8];
            }
            #pragma unroll
            for (int nf = 0; nf < 8; nf++) {
                int nc = warp_n * 64 + nf * 8 + g;
                unsigned bh[2] = { Bh[ks + tq][nc], Bh[ks + tq + 4][nc] };
                unsigned bl[2] = { Bl[ks + tq][nc], Bl[ks + tq + 4][nc] };
                #pragma unroll
                for (int mf = 0; mf < 2; mf++) {
                    mma_tf32(acc[mf][nf], afh[mf], bh);
                    mma_tf32(acc[mf][nf], afh[mf], bl);
                    mma_tf32(acc[mf][nf], afl[mf], bh);
                }
            }
        }
        __syncthreads();
    }

    // fused epilogue: bias, scale, mask
    #pragma unroll
    for (int mf = 0; mf < 2; mf++) {
        int row0 = q0 + warp_m * 32 + mf * 16 + g;
        #pragma unroll
        for (int nf = 0; nf < 8; nf++) {
            int lc  = warp_n * 64 + nf * 8 + 2 * tq;
            int col = k0c + lc;
            float ka = ks_s[lc], kb = ks_s[lc + 1];
            #pragma unroll
            for (int r = 0; r < 2; r++) {
                int qi = row0 + r * 8;
                size_t rowbm = ((size_t)b * TT + qi) * TT + col;
                float2 bs2 = *(const float2*)&g_bs[rowbm];
                float2 mk2 = *(const float2*)&masks[rowbm];
                float v0 = (acc[mf][nf][2 * r]     + bs2.x * ka) * 0.125f - mk2.x * FBIG;
                float v1 = (acc[mf][nf][2 * r + 1] + bs2.y * kb) * 0.125f - mk2.y * FBIG;
                *(float2*)&g_alpha[((size_t)z * TT + qi) * TT + col] = make_float2(v0, v1);
            }
        }
    }
}

// ---------------- softmax: float4 + fast exp, one block per row ----------------
__global__ void softmax_kernel() {
    __shared__ float smax[8];
    __shared__ float ssum[8];
    float4* p = (float4*)(g_alpha + (size_t)blockIdx.x * TT);
    const int tid = threadIdx.x;                 // 256
    const int lane = tid & 31, wid = tid >> 5;
    float4 x = p[tid];
    float mx = fmaxf(fmaxf(x.x, x.y), fmaxf(x.z, x.w));
    #pragma unroll
    for (int o = 16; o; o >>= 1) mx = fmaxf(mx, __shfl_xor_sync(0xffffffffu, mx, o));
    if (lane == 0) smax[wid] = mx;
    __syncthreads();
    mx = smax[0];
    #pragma unroll
    for (int w = 1; w < 8; w++) mx = fmaxf(mx, smax[w]);
    x.x = fexp(x.x - mx); x.y = fexp(x.y - mx);
    x.z = fexp(x.z - mx); x.w = fexp(x.w - mx);
    float s = x.x + x.y + x.z + x.w;
    #pragma unroll
    for (int o = 16; o; o >>= 1) s += __shfl_xor_sync(0xffffffffu, s, o);
    if (lane == 0) ssum[wid] = s;
    __syncthreads();
    float tot = 0.f;
    #pragma unroll
    for (int w = 0; w < 8; w++) tot += ssum[w];
    float inv = 1.0f / tot;
    x.x *= inv; x.y *= inv; x.z *= inv; x.w *= inv;
    p[tid] = x;
}

// ---------------- context TF32: ctx[b,q,h,a] = sum_k alpha[b,h,q,k] * v[b,k,h,a] ----
// 128(q) x 64(a) tile, K-dim 1024.  Warp tile 32x32.
__global__ __launch_bounds__(256, 2)
void context_tf32_kernel() {
    __shared__ unsigned Ah[16][136], Al[16][136];   // alpha: [k][q]
    __shared__ unsigned Bh[16][72],  Bl[16][72];    // V: [k][a]
    const int z = blockIdx.y;                 // b*H + h
    const int b = z >> 4, h = z & 15;
    const int q0 = blockIdx.x * 128;
    const int tid = threadIdx.x;
    const int wid = tid >> 5, lane = tid & 31;
    const int g = lane >> 2, tq = lane & 3;
    const int warp_m = wid >> 1, warp_n = wid & 1;
    const float* arow  = g_alpha + ((size_t)z * TT + q0) * TT;
    const float* vbase = g_v + (size_t)(b * TT) * HA + h * AD;

    float acc[2][4][4];
    #pragma unroll
    for (int mf = 0; mf < 2; mf++)
        #pragma unroll
        for (int nf = 0; nf < 4; nf++)
            #pragma unroll
            for (int r = 0; r < 4; r++) acc[mf][nf][r] = 0.f;

    for (int k0 = 0; k0 < TT; k0 += 16) {
        // stage alpha tile 128 x 16
        #pragma unroll
        for (int it = 0; it < 2; it++) {
            int idx = tid + it * 256;           // 0..511
            int row = idx >> 2, kg = (idx & 3) * 4;
            float4 v = *(const float4*)&arow[(size_t)row * TT + k0 + kg];
            float vv[4] = { v.x, v.y, v.z, v.w };
            #pragma unroll
            for (int j = 0; j < 4; j++) {
                unsigned hh = cvt_tf32(vv[j]);
                Ah[kg + j][row] = hh;
                Al[kg + j][row] = cvt_tf32(vv[j] - __uint_as_float(hh));
            }
        }
        // stage V tile 16 x 64
        {
            int krow = tid >> 4, ng = (tid & 15) * 4;
            float4 v = *(const float4*)&vbase[(size_t)(k0 + krow) * HA + ng];
            uint4 hh, ll;
            hh.x = cvt_tf32(v.x); ll.x = cvt_tf32(v.x - __uint_as_float(hh.x));
            hh.y = cvt_tf32(v.y); ll.y = cvt_tf32(v.y - __uint_as_float(hh.y));
            hh.z = cvt_tf32(v.z); ll.z = cvt_tf32(v.z - __uint_as_float(hh.z));
            hh.w = cvt_tf32(v.w); ll.w = cvt_tf32(v.w - __uint_as_float(hh.w));
            *(uint4*)&Bh[krow][ng] = hh;
            *(uint4*)&Bl[krow][ng] = ll;
        }
        __syncthreads();
        #pragma unroll
        for (int ks = 0; ks < 16; ks += 8) {
            unsigned afh[2][4], afl[2][4];
            #pragma unroll
            for (int mf = 0; mf < 2; mf++) {
                int mr = warp_m * 32 + mf * 16 + g;
                afh[mf][0] = Ah[ks + tq][mr];     afh[mf][1] = Ah[ks + tq][mr + 8];
                afh[mf][2] = Ah[ks + tq + 4][mr]; afh[mf][3] = Ah[ks + tq + 4][mr + 8];
                afl[mf][0] = Al[ks + tq][mr];     afl[mf][1] = Al[ks + tq][mr + 8];
                afl[mf][2] = Al[ks + tq + 4][mr]; afl[mf][3] = Al[ks + tq + 4][mr + 8];
            }
            #pragma unroll
            for (int nf = 0; nf < 4; nf++) {
                int nc = warp_n * 32 + nf * 8 + g;
                unsigned bh[2] = { Bh[ks + tq][nc], Bh[ks + tq + 4][nc] };
                unsigned bl[2] = { Bl[ks + tq][nc], Bl[ks + tq + 4][nc] };
                #pragma unroll
                for (int mf = 0; mf < 2; mf++) {
                    mma_tf32(acc[mf][nf], afh[mf], bh);
                    mma_tf32(acc[mf][nf], afh[mf], bl);
                    mma_tf32(acc[mf][nf], afl[mf], bh);
                }
            }
        }
        __syncthreads();
    }

    #pragma unroll
    for (int mf = 0; mf < 2; mf++) {
        int row0 = q0 + warp_m * 32 + mf * 16 + g;
        #pragma unroll
        for (int nf = 0; nf < 4; nf++) {
            int col = warp_n * 32 + nf * 8 + 2 * tq;
            *(float2*)&g_ctx[(size_t)(b * TT + row0) * HA + h * AD + col] =
                make_float2(acc[mf][nf][0], acc[mf][nf][1]);
            *(float2*)&g_ctx[(size_t)(b * TT + row0 + 8) * HA + h * AD + col] =
                make_float2(acc[mf][nf][2], acc[mf][nf][3]);
        }
    }
}

// ---------------- launch ----------------
extern "C" void kernel_launch(void* const* d_in, const int* in_sizes, int n_in,
                              void* d_out, int out_size) {
    const float* states     = (const float*)d_in[0];
    const float* key_states = (const float*)d_in[1];
    const float* masks      = (const float*)d_in[2];
    const int*   ab32       = (const int*)d_in[3];
    const float* Wq         = (const float*)d_in[4];
    const float* Wk         = (const float*)d_in[5];
    const float* Wv         = (const float*)d_in[6];
    const float* Wout       = (const float*)d_in[7];
    const float* embs       = (const float*)d_in[8];
    const float* scal       = (const float*)d_in[9];
    float* out              = (float*)d_out;

    dim3 gemm_grid(HA / 128, BT / 128);   // (8, 64)

    // QKV projections — TF32 tensor cores (3xTF32)
    tf32_gemm_kernel<<<gemm_grid, 256>>>(states,     Wq, nullptr, 0, 0, BT, HA, DD);
    tf32_gemm_kernel<<<gemm_grid, 256>>>(key_states, Wk, nullptr, 0, 1, BT, HA, DD);
    tf32_gemm_kernel<<<gemm_grid, 256>>>(key_states, Wv, nullptr, 0, 2, BT, HA, DD);

    // ksum
    ksum_kernel<<<(BT * HH + 255) / 256, 256>>>();

    // edge-bias detect + projection + deterministic scatter
    detect_kernel<<<1, 1>>>(ab32);
    proj_kernel<<<1, 32>>>(embs, scal);
    zero_bs_kernel<<<(BB * TT * TT / 4 + 255) / 256, 256>>>();
    scatter_pass1_kernel<<<(NEDGE + 255) / 256, 256>>>(ab32);
    scatter_pass2_kernel<<<(NEDGE + 255) / 256, 256>>>(ab32);

    // scores (TF32) + softmax
    dim3 sc_grid(TT / 128, TT / 128, BB * HH);   // (8, 8, 128)
    scores_tf32_kernel<<<sc_grid, 256>>>(masks);
    softmax_kernel<<<BB * HH * TT, 256>>>();

    // context (TF32)
    dim3 cx_grid(TT / 128, BB * HH);             // (8, 128)
    context_tf32_kernel<<<cx_grid, 256>>>();

    // output projection — TF32 tensor cores
    tf32_gemm_kernel<<<gemm_grid, 256>>>(nullptr, Wout, out, 1, 3, BT, DD, HA);
}

// round 11
// speedup vs baseline: 1.6499x; 1.0055x over previous
#include <cuda_runtime.h>
#include <math.h>

#define BB 8
#define TT 1024
#define DD 1024
#define HH 16
#define AD 64
#define BT (BB*TT)      /* 8192 */
#define HA (HH*AD)      /* 1024 */
#define NEDGE 262144
#define BIASDIM 32
#define FBIG 3.402823466e+38f

// ---------------- scratch (no allocations allowed) ----------------
__device__ float g_q[BT*HA];
__device__ float g_k[BT*HA];
__device__ float g_v[BT*HA];
__device__ float g_ctx[BT*HA];
__device__ float g_ksum[BT*HH];        // [bt][h]
__device__ float g_bs[BB*TT*TT];
__device__ int   g_winner[BB*TT*TT];
__device__ float g_alpha[(size_t)BB*HH*TT*TT];
__device__ float2 g_rowstat[BB*HH*TT];  // (rowmax, 1/sum)
__device__ float g_proj[BIASDIM];
__device__ int   g_is64;

// ---------------- tf32 helpers ----------------
__device__ __forceinline__ unsigned cvt_tf32(float x) {
    unsigned r; asm("cvt.rna.tf32.f32 %0, %1;" : "=r"(r) : "f"(x)); return r;
}
__device__ __forceinline__ void mma_tf32(float (&d)[4], const unsigned (&a)[4],
                                         const unsigned (&b)[2]) {
    asm("mma.sync.aligned.m16n8k8.row.col.f32.tf32.tf32.f32 "
        "{%0,%1,%2,%3}, {%4,%5,%6,%7}, {%8,%9}, {%0,%1,%2,%3};"
        : "+f"(d[0]), "+f"(d[1]), "+f"(d[2]), "+f"(d[3])
        : "r"(a[0]), "r"(a[1]), "r"(a[2]), "r"(a[3]), "r"(b[0]), "r"(b[1]));
}

// ---------------- fast exp (FMA-only, for x <= 0) ----------------
__device__ __forceinline__ float fexp(float x) {
    float y = fmaxf(x * 1.4426950408889634f, -126.0f);
    int   i = __float2int_rn(y);
    float f = y - (float)i;
    float p = 1.5403530e-4f;
    p = fmaf(p, f, 1.3333558e-3f);
    p = fmaf(p, f, 9.6181291e-3f);
    p = fmaf(p, f, 5.5504109e-2f);
    p = fmaf(p, f, 2.4022651e-1f);
    p = fmaf(p, f, 6.9314718e-1f);
    p = fmaf(p, f, 1.0f);
    return p * __int_as_float((i + 127) << 23);
}

// ---------------- dtype detector for attention_bias ----------------
__global__ void detect_kernel(const int* __restrict__ ab32) {
    int ok = 1;
    #pragma unroll
    for (int i = 0; i < 64; i++) ok &= (ab32[2 * i + 1] == 0);
    g_is64 = ok;
}

// ---------------- proj[et] = bias_embs[et] . bias_scalar ----------------
__global__ void proj_kernel(const float* __restrict__ embs, const float* __restrict__ scal) {
    int et = threadIdx.x;
    if (et >= BIASDIM) return;
    float s = 0.f;
    #pragma unroll
    for (int a = 0; a < AD; a++) s += embs[et * AD + a] * scal[a];
    g_proj[et] = s;
}

// ---------------- TF32 tensor-core GEMM: C[M,N] = A[M,K] @ B[K,N] ----------------
__global__ __launch_bounds__(256, 2)
void tf32_gemm_kernel(const float* __restrict__ Aext, const float* __restrict__ Bm,
                      float* __restrict__ Cext, int which_a, int which_c,
                      int M, int N, int K) {
    const float* A = (which_a == 1) ? g_ctx : Aext;
    float* C = (which_c == 0) ? g_q : (which_c == 1) ? g_k : (which_c == 2) ? g_v : Cext;
    __shared__ unsigned Ah[16][136], Al[16][136];   // [k][m]
    __shared__ unsigned Bh[16][136], Bl[16][136];   // [k][n]
    const int tid = threadIdx.x;
    const int wid = tid >> 5, lane = tid & 31;
    const int g = lane >> 2, tq = lane & 3;
    const int warp_m = wid >> 1, warp_n = wid & 1;
    const int m0 = blockIdx.y * 128, n0 = blockIdx.x * 128;

    float acc[2][8][4];
    #pragma unroll
    for (int mf = 0; mf < 2; mf++)
        #pragma unroll
        for (int nf = 0; nf < 8; nf++)
            #pragma unroll
            for (int r = 0; r < 4; r++) acc[mf][nf][r] = 0.f;

    for (int k0 = 0; k0 < K; k0 += 16) {
        #pragma unroll
        for (int it = 0; it < 2; it++) {
            int idx = tid + it * 256;           // 0..511
            int row = idx >> 2, kg = (idx & 3) * 4;
            float4 v = *(const float4*)&A[(size_t)(m0 + row) * K + k0 + kg];
            float vv[4] = { v.x, v.y, v.z, v.w };
            #pragma unroll
            for (int j = 0; j < 4; j++) {
                unsigned h = cvt_tf32(vv[j]);
                Ah[kg + j][row] = h;
                Al[kg + j][row] = cvt_tf32(vv[j] - __uint_as_float(h));
            }
        }
        #pragma unroll
        for (int it = 0; it < 2; it++) {
            int idx = tid + it * 256;           // 0..511
            int row = idx >> 5, ng = (idx & 31) * 4;
            float4 v = *(const float4*)&Bm[(size_t)(k0 + row) * N + n0 + ng];
            uint4 h, l;
            h.x = cvt_tf32(v.x); l.x = cvt_tf32(v.x - __uint_as_float(h.x));
            h.y = cvt_tf32(v.y); l.y = cvt_tf32(v.y - __uint_as_float(h.y));
            h.z = cvt_tf32(v.z); l.z = cvt_tf32(v.z - __uint_as_float(h.z));
            h.w = cvt_tf32(v.w); l.w = cvt_tf32(v.w - __uint_as_float(h.w));
            *(uint4*)&Bh[row][ng] = h;
            *(uint4*)&Bl[row][ng] = l;
        }
        __syncthreads();

        #pragma unroll
        for (int ks = 0; ks < 16; ks += 8) {
            unsigned afh[2][4], afl[2][4];
            #pragma unroll
            for (int mf = 0; mf < 2; mf++) {
                int mr = warp_m * 32 + mf * 16 + g;
                afh[mf][0] = Ah[ks + tq][mr];     afh[mf][1] = Ah[ks + tq][mr + 8];
                afh[mf][2] = Ah[ks + tq + 4][mr]; afh[mf][3] = Ah[ks + tq + 4][mr + 8];
                afl[mf][0] = Al[ks + tq][mr];     afl[mf][1] = Al[ks + tq][mr + 8];
                afl[mf][2] = Al[ks + tq + 4][mr]; afl[mf][3] = Al[ks + tq + 4][mr + 8];
            }
            #pragma unroll
            for (int nf = 0; nf < 8; nf++) {
                int nc = warp_n * 64 + nf * 8 + g;
                unsigned bh[2] = { Bh[ks + tq][nc], Bh[ks + tq + 4][nc] };
                unsigned bl[2] = { Bl[ks + tq][nc], Bl[ks + tq + 4][nc] };
                #pragma unroll
                for (int mf = 0; mf < 2; mf++) {
                    mma_tf32(acc[mf][nf], afh[mf], bh);
                    mma_tf32(acc[mf][nf], afh[mf], bl);
                    mma_tf32(acc[mf][nf], afl[mf], bh);
                }
            }
        }
        __syncthreads();
    }

    #pragma unroll
    for (int mf = 0; mf < 2; mf++) {
        int row0 = m0 + warp_m * 32 + mf * 16 + g;
        #pragma unroll
        for (int nf = 0; nf < 8; nf++) {
            int col = n0 + warp_n * 64 + nf * 8 + 2 * tq;
            *(float2*)&C[(size_t)row0 * N + col] =
                make_float2(acc[mf][nf][0], acc[mf][nf][1]);
            *(float2*)&C[(size_t)(row0 + 8) * N + col] =
                make_float2(acc[mf][nf][2], acc[mf][nf][3]);
        }
    }
}

// ---------------- ksum[bt][h] = sum_a k[b,t,h,a] ----------------
__global__ void ksum_kernel() {
    int idx = blockIdx.x * blockDim.x + threadIdx.x;   // bt*H + h
    if (idx >= BT * HH) return;
    int bt = idx / HH, h = idx % HH;
    const float4* p = reinterpret_cast<const float4*>(&g_k[(size_t)bt * HA + h * AD]);
    float s = 0.f;
    #pragma unroll
    for (int i = 0; i < AD / 4; i++) { float4 v4 = p[i]; s += v4.x + v4.y + v4.z + v4.w; }
    g_ksum[idx] = s;
}

// ---------------- zero dense bias + winner scratch ----------------
__global__ void zero_bs_kernel() {
    int i = blockIdx.x * blockDim.x + threadIdx.x;
    if (i < BB * TT * TT / 4) {
        ((float4*)g_bs)[i] = make_float4(0.f, 0.f, 0.f, 0.f);
        ((int4*)g_winner)[i] = make_int4(-1, -1, -1, -1);
    }
}

// ---------------- decode edge e ----------------
__device__ __forceinline__ bool decode_edge(const int* __restrict__ ab32, int e,
                                            int& et, int& b, int& qi, int& ki) {
    if (g_is64) {
        const long long* ab = (const long long*)ab32;
        et = (int)ab[4 * e + 0]; b  = (int)ab[4 * e + 1];
        qi = (int)ab[4 * e + 2]; ki = (int)ab[4 * e + 3];
    } else {
        et = ab32[4 * e + 0]; b  = ab32[4 * e + 1];
        qi = ab32[4 * e + 2]; ki = ab32[4 * e + 3];
    }
    return !((unsigned)et >= BIASDIM || (unsigned)b >= BB ||
             (unsigned)qi >= TT || (unsigned)ki >= TT);
}

__global__ void scatter_pass1_kernel(const int* __restrict__ ab32) {
    int e = blockIdx.x * blockDim.x + threadIdx.x;
    if (e >= NEDGE) return;
    int et, b, qi, ki;
    if (!decode_edge(ab32, e, et, b, qi, ki)) return;
    atomicMax(&g_winner[((size_t)b * TT + qi) * TT + ki], e);
}

__global__ void scatter_pass2_kernel(const int* __restrict__ ab32) {
    int e = blockIdx.x * blockDim.x + threadIdx.x;
    if (e >= NEDGE) return;
    int et, b, qi, ki;
    if (!decode_edge(ab32, e, et, b, qi, ki)) return;
    size_t slot = ((size_t)b * TT + qi) * TT + ki;
    if (g_winner[slot] == e) g_bs[slot] = g_proj[et];
}

// ---------------- scores TF32: alpha = (QK^T + bs*ksum)*0.125 - mask*BIG ----------
__global__ __launch_bounds__(256, 2)
void scores_tf32_kernel(const float* __restrict__ masks) {
    __shared__ unsigned Ah[16][136], Al[16][136];   // Q: [a][q]
    __shared__ unsigned Bh[16][136], Bl[16][136];   // K: [a][k]
    __shared__ float ks_s[128];
    const int z = blockIdx.z;                 // b*H + h
    const int b = z >> 4, h = z & 15;
    const int q0 = blockIdx.y * 128, k0c = blockIdx.x * 128;
    const int tid = threadIdx.x;
    const int wid = tid >> 5, lane = tid & 31;
    const int g = lane >> 2, tq = lane & 3;
    const int warp_m = wid >> 1, warp_n = wid & 1;
    const float* qbase = g_q + (size_t)(b * TT + q0)  * HA + h * AD;
    const float* kbase = g_k + (size_t)(b * TT + k0c) * HA + h * AD;
    if (tid < 128) ks_s[tid] = g_ksum[(size_t)(b * TT + k0c + tid) * HH + h];

    float acc[2][8][4];
    #pragma unroll
    for (int mf = 0; mf < 2; mf++)
        #pragma unroll
        for (int nf = 0; nf < 8; nf++)
            #pragma unroll
            for (int r = 0; r < 4; r++) acc[mf][nf][r] = 0.f;

    for (int a0 = 0; a0 < AD; a0 += 16) {
        #pragma unroll
        for (int it = 0; it < 2; it++) {
            int idx = tid + it * 256;           // 0..511
            int row = idx >> 2, kg = (idx & 3) * 4;
            float4 v = *(const float4*)&qbase[(size_t)row * HA + a0 + kg];
            float4 w = *(const float4*)&kbase[(size_t)row * HA + a0 + kg];
            float vv[4] = { v.x, v.y, v.z, v.w };
            float ww[4] = { w.x, w.y, w.z, w.w };
            #pragma unroll
            for (int j = 0; j < 4; j++) {
                unsigned hq = cvt_tf32(vv[j]);
                Ah[kg + j][row] = hq;
                Al[kg + j][row] = cvt_tf32(vv[j] - __uint_as_float(hq));
                unsigned hk = cvt_tf32(ww[j]);
                Bh[kg + j][row] = hk;
                Bl[kg + j][row] = cvt_tf32(ww[j] - __uint_as_float(hk));
            }
        }
        __syncthreads();
        #pragma unroll
        for (int ks = 0; ks < 16; ks += 8) {
            unsigned afh[2][4], afl[2][4];
            #pragma unroll
            for (int mf = 0; mf < 2; mf++) {
                int mr = warp_m * 32 + mf * 16 + g;
                afh[mf][0] = Ah[ks + tq][mr];     afh[mf][1] = Ah[ks + tq][mr + 8];
                afh[mf][2] = Ah[ks + tq + 4][mr]; afh[mf][3] = Ah[ks + tq + 4][mr + 8];
                afl[mf][0] = Al[ks + tq][mr];     afl[mf][1] = Al[ks + tq][mr + 8];
                afl[mf][2] = Al[ks + tq + 4][mr]; afl[mf][3] = Al[ks + tq + 4][mr + 8];
            }
            #pragma unroll
            for (int nf = 0; nf < 8; nf++) {
                int nc = warp_n * 64 + nf * 8 + g;
                unsigned bh[2] = { Bh[ks + tq][nc], Bh[ks + tq + 4][nc] };
                unsigned bl[2] = { Bl[ks + tq][nc], Bl[ks + tq + 4][nc] };
                #pragma unroll
                for (int mf = 0; mf < 2; mf++) {
                    mma_tf32(acc[mf][nf], afh[mf], bh);
                    mma_tf32(acc[mf][nf], afh[mf], bl);
                    mma_tf32(acc[mf][nf], afl[mf], bh);
                }
            }
        }
        __syncthreads();
    }

    #pragma unroll
    for (int mf = 0; mf < 2; mf++) {
        int row0 = q0 + warp_m * 32 + mf * 16 + g;
        #pragma unroll
        for (int nf = 0; nf < 8; nf++) {
            int lc  = warp_n * 64 + nf * 8 + 2 * tq;
            int col = k0c + lc;
            float ka = ks_s[lc], kb = ks_s[lc + 1];
            #pragma unroll
            for (int r = 0; r < 2; r++) {
                int qi = row0 + r * 8;
                size_t rowbm = ((size_t)b * TT + qi) * TT + col;
                float2 bs2 = *(const float2*)&g_bs[rowbm];
                float2 mk2 = *(const float2*)&masks[rowbm];
                float v0 = (acc[mf][nf][2 * r]     + bs2.x * ka) * 0.125f - mk2.x * FBIG;
                float v1 = (acc[mf][nf][2 * r + 1] + bs2.y * kb) * 0.125f - mk2.y * FBIG;
                *(float2*)&g_alpha[((size_t)z * TT + qi) * TT + col] = make_float2(v0, v1);
            }
        }
    }
}

// ---------------- rowstat: per row, (max, 1/sum(exp(x-max))) — read-only -------
__global__ void rowstat_kernel() {
    __shared__ float smax[8];
    __shared__ float ssum[8];
    const float4* p = (const float4*)(g_alpha + (size_t)blockIdx.x * TT);
    const int tid = threadIdx.x;                 // 256
    const int lane = tid & 31, wid = tid >> 5;
    float4 x = p[tid];
    float mx = fmaxf(fmaxf(x.x, x.y), fmaxf(x.z, x.w));
    #pragma unroll
    for (int o = 16; o; o >>= 1) mx = fmaxf(mx, __shfl_xor_sync(0xffffffffu, mx, o));
    if (lane == 0) smax[wid] = mx;
    __syncthreads();
    mx = smax[0];
    #pragma unroll
    for (int w = 1; w < 8; w++) mx = fmaxf(mx, smax[w]);
    float s = fexp(x.x - mx) + fexp(x.y - mx) + fexp(x.z - mx) + fexp(x.w - mx);
    #pragma unroll
    for (int o = 16; o; o >>= 1) s += __shfl_xor_sync(0xffffffffu, s, o);
    if (lane == 0) ssum[wid] = s;
    __syncthreads();
    if (tid == 0) {
        float tot = 0.f;
        #pragma unroll
        for (int w = 0; w < 8; w++) tot += ssum[w];
        g_rowstat[blockIdx.x] = make_float2(mx, 1.0f / tot);
    }
}

// ---------------- context TF32 + fused softmax normalize ----------------
// ctx[b,q,h,a] = inv[q] * sum_k exp(alpha[q,k]-mx[q]) * v[b,k,h,a]
__global__ __launch_bounds__(256, 2)
void context_tf32_kernel() {
    __shared__ unsigned Ah[16][136], Al[16][136];   // P: [k][q]
    __shared__ unsigned Bh[16][72],  Bl[16][72];    // V: [k][a]
    __shared__ float2 rs_s[128];
    const int z = blockIdx.y;                 // b*H + h
    const int b = z >> 4, h = z & 15;
    const int q0 = blockIdx.x * 128;
    const int tid = threadIdx.x;
    const int wid = tid >> 5, lane = tid & 31;
    const int g = lane >> 2, tq = lane & 3;
    const int warp_m = wid >> 1, warp_n = wid & 1;
    const float* arow  = g_alpha + ((size_t)z * TT + q0) * TT;
    const float* vbase = g_v + (size_t)(b * TT) * HA + h * AD;
    if (tid < 128) rs_s[tid] = g_rowstat[(size_t)z * TT + q0 + tid];
    __syncthreads();

    float acc[2][4][4];
    #pragma unroll
    for (int mf = 0; mf < 2; mf++)
        #pragma unroll
        for (int nf = 0; nf < 4; nf++)
            #pragma unroll
            for (int r = 0; r < 4; r++) acc[mf][nf][r] = 0.f;

    for (int k0 = 0; k0 < TT; k0 += 16) {
        // stage P tile 128 x 16 : p = exp(alpha - mx)
        #pragma unroll
        for (int it = 0; it < 2; it++) {
            int idx = tid + it * 256;           // 0..511
            int row = idx >> 2, kg = (idx & 3) * 4;
            float mx = rs_s[row].x;
            float4 v = *(const float4*)&arow[(size_t)row * TT + k0 + kg];
            float vv[4] = { fexp(v.x - mx), fexp(v.y - mx),
                            fexp(v.z - mx), fexp(v.w - mx) };
            #pragma unroll
            for (int j = 0; j < 4; j++) {
                unsigned hh = cvt_tf32(vv[j]);
                Ah[kg + j][row] = hh;
                Al[kg + j][row] = cvt_tf32(vv[j] - __uint_as_float(hh));
            }
        }
        // stage V tile 16 x 64
        {
            int krow = tid >> 4, ng = (tid & 15) * 4;
            float4 v = *(const float4*)&vbase[(size_t)(k0 + krow) * HA + ng];
            uint4 hh, ll;
            hh.x = cvt_tf32(v.x); ll.x = cvt_tf32(v.x - __uint_as_float(hh.x));
            hh.y = cvt_tf32(v.y); ll.y = cvt_tf32(v.y - __uint_as_float(hh.y));
            hh.z = cvt_tf32(v.z); ll.z = cvt_tf32(v.z - __uint_as_float(hh.z));
            hh.w = cvt_tf32(v.w); ll.w = cvt_tf32(v.w - __uint_as_float(hh.w));
            *(uint4*)&Bh[krow][ng] = hh;
            *(uint4*)&Bl[krow][ng] = ll;
        }
        __syncthreads();
        #pragma unroll
        for (int ks = 0; ks < 16; ks += 8) {
            unsigned afh[2][4], afl[2][4];
            #pragma unroll
            for (int mf = 0; mf < 2; mf++) {
                int mr = warp_m * 32 + mf * 16 + g;
                afh[mf][0] = Ah[ks + tq][mr];     afh[mf][1] = Ah[ks + tq][mr + 8];
                afh[mf][2] = Ah[ks + tq + 4][mr]; afh[mf][3] = Ah[ks + tq + 4][mr + 8];
                afl[mf][0] = Al[ks + tq][mr];     afl[mf][1] = Al[ks + tq][mr + 8];
                afl[mf][2] = Al[ks + tq + 4][mr]; afl[mf][3] = Al[ks + tq + 4][mr + 8];
            }
            #pragma unroll
            for (int nf = 0; nf < 4; nf++) {
                int nc = warp_n * 32 + nf * 8 + g;
                unsigned bh[2] = { Bh[ks + tq][nc], Bh[ks + tq + 4][nc] };
                unsigned bl[2] = { Bl[ks + tq][nc], Bl[ks + tq + 4][nc] };
                #pragma unroll
                for (int mf = 0; mf < 2; mf++) {
                    mma_tf32(acc[mf][nf], afh[mf], bh);
                    mma_tf32(acc[mf][nf], afh[mf], bl);
                    mma_tf32(acc[mf][nf], afl[mf], bh);
                }
            }
        }
        __syncthreads();
    }

    #pragma unroll
    for (int mf = 0; mf < 2; mf++) {
        int lr0 = warp_m * 32 + mf * 16 + g;       // local row in tile
        float inv0 = rs_s[lr0].y, inv1 = rs_s[lr0 + 8].y;
        int row0 = q0 + lr0;
        #pragma unroll
        for (int nf = 0; nf < 4; nf++) {
            int col = warp_n * 32 + nf * 8 + 2 * tq;
            *(float2*)&g_ctx[(size_t)(b * TT + row0) * HA + h * AD + col] =
                make_float2(acc[mf][nf][0] * inv0, acc[mf][nf][1] * inv0);
            *(float2*)&g_ctx[(size_t)(b * TT + row0 + 8) * HA + h * AD + col] =
                make_float2(acc[mf][nf][2] * inv1, acc[mf][nf][3] * inv1);
        }
    }
}

// ---------------- launch ----------------
extern "C" void kernel_launch(void* const* d_in, const int* in_sizes, int n_in,
                              void* d_out, int out_size) {
    const float* states     = (const float*)d_in[0];
    const float* key_states = (const float*)d_in[1];
    const float* masks      = (const float*)d_in[2];
    const int*   ab32       = (const int*)d_in[3];
    const float* Wq         = (const float*)d_in[4];
    const float* Wk         = (const float*)d_in[5];
    const float* Wv         = (const float*)d_in[6];
    const float* Wout       = (const float*)d_in[7];
    const float* embs       = (const float*)d_in[8];
    const float* scal       = (const float*)d_in[9];
    float* out              = (float*)d_out;

    dim3 gemm_grid(HA / 128, BT / 128);   // (8, 64)

    // QKV projections — TF32 tensor cores (3xTF32)
    tf32_gemm_kernel<<<gemm_grid, 256>>>(states,     Wq, nullptr, 0, 0, BT, HA, DD);
    tf32_gemm_kernel<<<gemm_grid, 256>>>(key_states, Wk, nullptr, 0, 1, BT, HA, DD);
    tf32_gemm_kernel<<<gemm_grid, 256>>>(key_states, Wv, nullptr, 0, 2, BT, HA, DD);

    // ksum
    ksum_kernel<<<(BT * HH + 255) / 256, 256>>>();

    // edge-bias detect + projection + deterministic scatter
    detect_kernel<<<1, 1>>>(ab32);
    proj_kernel<<<1, 32>>>(embs, scal);
    zero_bs_kernel<<<(BB * TT * TT / 4 + 255) / 256, 256>>>();
    scatter_pass1_kernel<<<(NEDGE + 255) / 256, 256>>>(ab32);
    scatter_pass2_kernel<<<(NEDGE + 255) / 256, 256>>>(ab32);

    // scores (TF32) + row stats (max, 1/sum)
    dim3 sc_grid(TT / 128, TT / 128, BB * HH);   // (8, 8, 128)
    scores_tf32_kernel<<<sc_grid, 256>>>(masks);
    rowstat_kernel<<<BB * HH * TT, 256>>>();

    // context (TF32, fused exp-normalize)
    dim3 cx_grid(TT / 128, BB * HH);             // (8, 128)
    context_tf32_kernel<<<cx_grid, 256>>>();

    // output projection — TF32 tensor cores
    tf32_gemm_kernel<<<gemm_grid, 256>>>(nullptr, Wout, out, 1, 3, BT, DD, HA);
}

// round 12
// speedup vs baseline: 2.6245x; 1.5907x over previous
#include <cuda_runtime.h>
#include <cuda_bf16.h>
#include <math.h>

#define BB 8
#define TT 1024
#define DD 1024
#define HH 16
#define AD 64
#define BT (BB*TT)      /* 8192 */
#define HA (HH*AD)      /* 1024 */
#define NEDGE 262144
#define BIASDIM 32
#define FBIG 3.402823466e+38f

// ---------------- scratch (no allocations allowed) ----------------
__device__ float g_q[BT*HA];
__device__ float g_k[BT*HA];
__device__ float g_v[BT*HA];
__device__ float g_ctx[BT*HA];
__device__ float g_ksum[BT*HH];        // [bt][h]
__device__ float g_bs[BB*TT*TT];
__device__ int   g_winner[BB*TT*TT];
__device__ float g_alpha[(size_t)BB*HH*TT*TT];
__device__ float2 g_rowstat[BB*HH*TT];  // (rowmax, 1/sum)
__device__ float g_proj[BIASDIM];
__device__ int   g_is64;

// ---------------- bf16 split helpers ----------------
// pack2bf: pack (x0 -> low half, x1 -> high half) as bf16x2; residuals out.
__device__ __forceinline__ unsigned pack2bf(float x0, float x1, float& r0, float& r1) {
    __nv_bfloat16 b0 = __float2bfloat16_rn(x0), b1 = __float2bfloat16_rn(x1);
    r0 = x0 - __bfloat162float(b0);
    r1 = x1 - __bfloat162float(b1);
    return ((unsigned)__bfloat16_as_ushort(b1) << 16) | (unsigned)__bfloat16_as_ushort(b0);
}
__device__ __forceinline__ unsigned pack2bf_o(float x0, float x1) {
    unsigned r; asm("cvt.rn.bf16x2.f32 %0, %1, %2;" : "=r"(r) : "f"(x1), "f"(x0)); return r;
}
// m16n8k16 bf16 mma, fp32 accumulate
__device__ __forceinline__ void mma_bf16(float (&d)[4], const unsigned (&a)[4],
                                         const unsigned (&b)[2]) {
    asm("mma.sync.aligned.m16n8k16.row.col.f32.bf16.bf16.f32 "
        "{%0,%1,%2,%3}, {%4,%5,%6,%7}, {%8,%9}, {%0,%1,%2,%3};"
        : "+f"(d[0]), "+f"(d[1]), "+f"(d[2]), "+f"(d[3])
        : "r"(a[0]), "r"(a[1]), "r"(a[2]), "r"(a[3]), "r"(b[0]), "r"(b[1]));
}

// ---------------- fast exp (FMA-only, for x <= 0) ----------------
__device__ __forceinline__ float fexp(float x) {
    float y = fmaxf(x * 1.4426950408889634f, -126.0f);
    int   i = __float2int_rn(y);
    float f = y - (float)i;
    float p = 1.5403530e-4f;
    p = fmaf(p, f, 1.3333558e-3f);
    p = fmaf(p, f, 9.6181291e-3f);
    p = fmaf(p, f, 5.5504109e-2f);
    p = fmaf(p, f, 2.4022651e-1f);
    p = fmaf(p, f, 6.9314718e-1f);
    p = fmaf(p, f, 1.0f);
    return p * __int_as_float((i + 127) << 23);
}

// ---------------- dtype detector for attention_bias ----------------
__global__ void detect_kernel(const int* __restrict__ ab32) {
    int ok = 1;
    #pragma unroll
    for (int i = 0; i < 64; i++) ok &= (ab32[2 * i + 1] == 0);
    g_is64 = ok;
}

// ---------------- proj[et] = bias_embs[et] . bias_scalar ----------------
__global__ void proj_kernel(const float* __restrict__ embs, const float* __restrict__ scal) {
    int et = threadIdx.x;
    if (et >= BIASDIM) return;
    float s = 0.f;
    #pragma unroll
    for (int a = 0; a < AD; a++) s += embs[et * AD + a] * scal[a];
    g_proj[et] = s;
}

// ---------------- BF16 tensor-core GEMM: C[M,N] = A[M,K] @ B[K,N] ----------------
// 3-term bf16 split: AhBh + AhBl + AlBh, fp32 accum.  Tile 128x128, BK=16.
__global__ __launch_bounds__(256, 2)
void bf16_gemm_kernel(const float* __restrict__ Aext, const float* __restrict__ Bm,
                      float* __restrict__ Cext, int which_a, int which_c,
                      int M, int N, int K) {
    const float* A = (which_a == 1) ? g_ctx : Aext;
    float* C = (which_c == 0) ? g_q : (which_c == 1) ? g_k : (which_c == 2) ? g_v : Cext;
    __shared__ unsigned Ahp[8][136], Alp[8][136];   // [kpair][m]
    __shared__ unsigned Bhp[8][136], Blp[8][136];   // [kpair][n]
    const int tid = threadIdx.x;
    const int wid = tid >> 5, lane = tid & 31;
    const int g = lane >> 2, tq = lane & 3;
    const int warp_m = wid >> 1, warp_n = wid & 1;
    const int m0 = blockIdx.y * 128, n0 = blockIdx.x * 128;

    float acc[2][8][4];
    #pragma unroll
    for (int mf = 0; mf < 2; mf++)
        #pragma unroll
        for (int nf = 0; nf < 8; nf++)
            #pragma unroll
            for (int r = 0; r < 4; r++) acc[mf][nf][r] = 0.f;

    for (int k0 = 0; k0 < K; k0 += 16) {
        // stage A 128x16: pairs along k lie inside the float4
        #pragma unroll
        for (int it = 0; it < 2; it++) {
            int idx = tid + it * 256;           // 0..511
            int row = idx >> 2, kg = (idx & 3) * 4, kp = kg >> 1;
            float4 v = *(const float4*)&A[(size_t)(m0 + row) * K + k0 + kg];
            float l0, l1, l2, l3;
            Ahp[kp][row]     = pack2bf(v.x, v.y, l0, l1);
            Ahp[kp + 1][row] = pack2bf(v.z, v.w, l2, l3);
            Alp[kp][row]     = pack2bf_o(l0, l1);
            Alp[kp + 1][row] = pack2bf_o(l2, l3);
        }
        // stage B 16x128: pack vertically across two k-rows
        {
            int kp = tid >> 5, ng = (tid & 31) * 4;
            const float* r0p = &Bm[(size_t)(k0 + 2 * kp) * N + n0 + ng];
            float4 r0 = *(const float4*)r0p;
            float4 r1 = *(const float4*)(r0p + N);
            float a0, a1, a2, a3, a4, a5, a6, a7;
            unsigned h0 = pack2bf(r0.x, r1.x, a0, a1);
            unsigned h1 = pack2bf(r0.y, r1.y, a2, a3);
            unsigned h2 = pack2bf(r0.z, r1.z, a4, a5);
            unsigned h3 = pack2bf(r0.w, r1.w, a6, a7);
            *(uint4*)&Bhp[kp][ng] = make_uint4(h0, h1, h2, h3);
            *(uint4*)&Blp[kp][ng] = make_uint4(pack2bf_o(a0, a1), pack2bf_o(a2, a3),
                                               pack2bf_o(a4, a5), pack2bf_o(a6, a7));
        }
        __syncthreads();

        unsigned afh[2][4], afl[2][4];
        #pragma unroll
        for (int mf = 0; mf < 2; mf++) {
            int mr = warp_m * 32 + mf * 16 + g;
            afh[mf][0] = Ahp[tq][mr];     afh[mf][1] = Ahp[tq][mr + 8];
            afh[mf][2] = Ahp[tq + 4][mr]; afh[mf][3] = Ahp[tq + 4][mr + 8];
            afl[mf][0] = Alp[tq][mr];     afl[mf][1] = Alp[tq][mr + 8];
            afl[mf][2] = Alp[tq + 4][mr]; afl[mf][3] = Alp[tq + 4][mr + 8];
        }
        #pragma unroll
        for (int nf = 0; nf < 8; nf++) {
            int nc = warp_n * 64 + nf * 8 + g;
            unsigned bh[2] = { Bhp[tq][nc], Bhp[tq + 4][nc] };
            unsigned bl[2] = { Blp[tq][nc], Blp[tq + 4][nc] };
            #pragma unroll
            for (int mf = 0; mf < 2; mf++) {
                mma_bf16(acc[mf][nf], afh[mf], bh);
                mma_bf16(acc[mf][nf], afh[mf], bl);
                mma_bf16(acc[mf][nf], afl[mf], bh);
            }
        }
        __syncthreads();
    }

    #pragma unroll
    for (int mf = 0; mf < 2; mf++) {
        int row0 = m0 + warp_m * 32 + mf * 16 + g;
        #pragma unroll
        for (int nf = 0; nf < 8; nf++) {
            int col = n0 + warp_n * 64 + nf * 8 + 2 * tq;
            *(float2*)&C[(size_t)row0 * N + col] =
                make_float2(acc[mf][nf][0], acc[mf][nf][1]);
            *(float2*)&C[(size_t)(row0 + 8) * N + col] =
                make_float2(acc[mf][nf][2], acc[mf][nf][3]);
        }
    }
}

// ---------------- ksum[bt][h] = sum_a k[b,t,h,a] ----------------
__global__ void ksum_kernel() {
    int idx = blockIdx.x * blockDim.x + threadIdx.x;   // bt*H + h
    if (idx >= BT * HH) return;
    int bt = idx / HH, h = idx % HH;
    const float4* p = reinterpret_cast<const float4*>(&g_k[(size_t)bt * HA + h * AD]);
    float s = 0.f;
    #pragma unroll
    for (int i = 0; i < AD / 4; i++) { float4 v4 = p[i]; s += v4.x + v4.y + v4.z + v4.w; }
    g_ksum[idx] = s;
}

// ---------------- zero dense bias + winner scratch ----------------
__global__ void zero_bs_kernel() {
    int i = blockIdx.x * blockDim.x + threadIdx.x;
    if (i < BB * TT * TT / 4) {
        ((float4*)g_bs)[i] = make_float4(0.f, 0.f, 0.f, 0.f);
        ((int4*)g_winner)[i] = make_int4(-1, -1, -1, -1);
    }
}

// ---------------- decode edge e ----------------
__device__ __forceinline__ bool decode_edge(const int* __restrict__ ab32, int e,
                                            int& et, int& b, int& qi, int& ki) {
    if (g_is64) {
        const long long* ab = (const long long*)ab32;
        et = (int)ab[4 * e + 0]; b  = (int)ab[4 * e + 1];
        qi = (int)ab[4 * e + 2]; ki = (int)ab[4 * e + 3];
    } else {
        et = ab32[4 * e + 0]; b  = ab32[4 * e + 1];
        qi = ab32[4 * e + 2]; ki = ab32[4 * e + 3];
    }
    return !((unsigned)et >= BIASDIM || (unsigned)b >= BB ||
             (unsigned)qi >= TT || (unsigned)ki >= TT);
}

__global__ void scatter_pass1_kernel(const int* __restrict__ ab32) {
    int e = blockIdx.x * blockDim.x + threadIdx.x;
    if (e >= NEDGE) return;
    int et, b, qi, ki;
    if (!decode_edge(ab32, e, et, b, qi, ki)) return;
    atomicMax(&g_winner[((size_t)b * TT + qi) * TT + ki], e);
}

__global__ void scatter_pass2_kernel(const int* __restrict__ ab32) {
    int e = blockIdx.x * blockDim.x + threadIdx.x;
    if (e >= NEDGE) return;
    int et, b, qi, ki;
    if (!decode_edge(ab32, e, et, b, qi, ki)) return;
    size_t slot = ((size_t)b * TT + qi) * TT + ki;
    if (g_winner[slot] == e) g_bs[slot] = g_proj[et];
}

// ---------------- scores BF16: alpha = (QK^T + bs*ksum)*0.125 - mask*BIG ----------
// C[q,k] = sum_a Q[q,a]*K[k,a]; both operands a-contiguous -> A-style staging.
__global__ __launch_bounds__(256, 2)
void scores_bf16_kernel(const float* __restrict__ masks) {
    __shared__ unsigned Ahp[8][136], Alp[8][136];   // Q: [apair][q]
    __shared__ unsigned Bhp[8][136], Blp[8][136];   // K: [apair][k]
    __shared__ float ks_s[128];
    const int z = blockIdx.z;                 // b*H + h
    const int b = z >> 4, h = z & 15;
    const int q0 = blockIdx.y * 128, k0c = blockIdx.x * 128;
    const int tid = threadIdx.x;
    const int wid = tid >> 5, lane = tid & 31;
    const int g = lane >> 2, tq = lane & 3;
    const int warp_m = wid >> 1, warp_n = wid & 1;
    const float* qbase = g_q + (size_t)(b * TT + q0)  * HA + h * AD;
    const float* kbase = g_k + (size_t)(b * TT + k0c) * HA + h * AD;
    if (tid < 128) ks_s[tid] = g_ksum[(size_t)(b * TT + k0c + tid) * HH + h];

    float acc[2][8][4];
    #pragma unroll
    for (int mf = 0; mf < 2; mf++)
        #pragma unroll
        for (int nf = 0; nf < 8; nf++)
            #pragma unroll
            for (int r = 0; r < 4; r++) acc[mf][nf][r] = 0.f;

    for (int a0 = 0; a0 < AD; a0 += 16) {
        #pragma unroll
        for (int it = 0; it < 2; it++) {
            int idx = tid + it * 256;           // 0..511
            int row = idx >> 2, kg = (idx & 3) * 4, kp = kg >> 1;
            float4 v = *(const float4*)&qbase[(size_t)row * HA + a0 + kg];
            float4 w = *(const float4*)&kbase[(size_t)row * HA + a0 + kg];
            float l0, l1, l2, l3;
            Ahp[kp][row]     = pack2bf(v.x, v.y, l0, l1);
            Alp[kp][row]     = pack2bf_o(l0, l1);
            Ahp[kp + 1][row] = pack2bf(v.z, v.w, l2, l3);
            Alp[kp + 1][row] = pack2bf_o(l2, l3);
            Bhp[kp][row]     = pack2bf(w.x, w.y, l0, l1);
            Blp[kp][row]     = pack2bf_o(l0, l1);
            Bhp[kp + 1][row] = pack2bf(w.z, w.w, l2, l3);
            Blp[kp + 1][row] = pack2bf_o(l2, l3);
        }
        __syncthreads();
        unsigned afh[2][4], afl[2][4];
        #pragma unroll
        for (int mf = 0; mf < 2; mf++) {
            int mr = warp_m * 32 + mf * 16 + g;
            afh[mf][0] = Ahp[tq][mr];     afh[mf][1] = Ahp[tq][mr + 8];
            afh[mf][2] = Ahp[tq + 4][mr]; afh[mf][3] = Ahp[tq + 4][mr + 8];
            afl[mf][0] = Alp[tq][mr];     afl[mf][1] = Alp[tq][mr + 8];
            afl[mf][2] = Alp[tq + 4][mr]; afl[mf][3] = Alp[tq + 4][mr + 8];
        }
        #pragma unroll
        for (int nf = 0; nf < 8; nf++) {
            int nc = warp_n * 64 + nf * 8 + g;
            unsigned bh[2] = { Bhp[tq][nc], Bhp[tq + 4][nc] };
            unsigned bl[2] = { Blp[tq][nc], Blp[tq + 4][nc] };
            #pragma unroll
            for (int mf = 0; mf < 2; mf++) {
                mma_bf16(acc[mf][nf], afh[mf], bh);
                mma_bf16(acc[mf][nf], afh[mf], bl);
                mma_bf16(acc[mf][nf], afl[mf], bh);
            }
        }
        __syncthreads();
    }

    #pragma unroll
    for (int mf = 0; mf < 2; mf++) {
        int row0 = q0 + warp_m * 32 + mf * 16 + g;
        #pragma unroll
        for (int nf = 0; nf < 8; nf++) {
            int lc  = warp_n * 64 + nf * 8 + 2 * tq;
            int col = k0c + lc;
            float ka = ks_s[lc], kb = ks_s[lc + 1];
            #pragma unroll
            for (int r = 0; r < 2; r++) {
                int qi = row0 + r * 8;
                size_t rowbm = ((size_t)b * TT + qi) * TT + col;
                float2 bs2 = *(const float2*)&g_bs[rowbm];
                float2 mk2 = *(const float2*)&masks[rowbm];
                float v0 = (acc[mf][nf][2 * r]     + bs2.x * ka) * 0.125f - mk2.x * FBIG;
                float v1 = (acc[mf][nf][2 * r + 1] + bs2.y * kb) * 0.125f - mk2.y * FBIG;
                *(float2*)&g_alpha[((size_t)z * TT + qi) * TT + col] = make_float2(v0, v1);
            }
        }
    }
}

// ---------------- rowstat: per row, (max, 1/sum(exp(x-max))) -------------------
__global__ void rowstat_kernel() {
    __shared__ float smax[8];
    __shared__ float ssum[8];
    const float4* p = (const float4*)(g_alpha + (size_t)blockIdx.x * TT);
    const int tid = threadIdx.x;                 // 256
    const int lane = tid & 31, wid = tid >> 5;
    float4 x = p[tid];
    float mx = fmaxf(fmaxf(x.x, x.y), fmaxf(x.z, x.w));
    #pragma unroll
    for (int o = 16; o; o >>= 1) mx = fmaxf(mx, __shfl_xor_sync(0xffffffffu, mx, o));
    if (lane == 0) smax[wid] = mx;
    __syncthreads();
    mx = smax[0];
    #pragma unroll
    for (int w = 1; w < 8; w++) mx = fmaxf(mx, smax[w]);
    float s = fexp(x.x - mx) + fexp(x.y - mx) + fexp(x.z - mx) + fexp(x.w - mx);
    #pragma unroll
    for (int o = 16; o; o >>= 1) s += __shfl_xor_sync(0xffffffffu, s, o);
    if (lane == 0) ssum[wid] = s;
    __syncthreads();
    if (tid == 0) {
        float tot = 0.f;
        #pragma unroll
        for (int w = 0; w < 8; w++) tot += ssum[w];
        g_rowstat[blockIdx.x] = make_float2(mx, 1.0f / tot);
    }
}

// ---------------- context BF16 + fused softmax normalize ----------------
__global__ __launch_bounds__(256, 2)
void context_bf16_kernel() {
    __shared__ unsigned Ahp[8][136], Alp[8][136];   // P: [kpair][q]
    __shared__ unsigned Bhp[8][72],  Blp[8][72];    // V: [kpair][a]
    __shared__ float2 rs_s[128];
    const int z = blockIdx.y;                 // b*H + h
    const int b = z >> 4, h = z & 15;
    const int q0 = blockIdx.x * 128;
    const int tid = threadIdx.x;
    const int wid = tid >> 5, lane = tid & 31;
    const int g = lane >> 2, tq = lane & 3;
    const int warp_m = wid >> 1, warp_n = wid & 1;
    const float* arow  = g_alpha + ((size_t)z * TT + q0) * TT;
    const float* vbase = g_v + (size_t)(b * TT) * HA + h * AD;
    if (tid < 128) rs_s[tid] = g_rowstat[(size_t)z * TT + q0 + tid];
    __syncthreads();

    float acc[2][4][4];
    #pragma unroll
    for (int mf = 0; mf < 2; mf++)
        #pragma unroll
        for (int nf = 0; nf < 4; nf++)
            #pragma unroll
            for (int r = 0; r < 4; r++) acc[mf][nf][r] = 0.f;

    for (int k0 = 0; k0 < TT; k0 += 16) {
        // stage P 128x16 : p = exp(alpha - mx)
        #pragma unroll
        for (int it = 0; it < 2; it++) {
            int idx = tid + it * 256;           // 0..511
            int row = idx >> 2, kg = (idx & 3) * 4, kp = kg >> 1;
            float mx = rs_s[row].x;
            float4 v = *(const float4*)&arow[(size_t)row * TT + k0 + kg];
            float p0 = fexp(v.x - mx), p1 = fexp(v.y - mx);
            float p2 = fexp(v.z - mx), p3 = fexp(v.w - mx);
            float l0, l1, l2, l3;
            Ahp[kp][row]     = pack2bf(p0, p1, l0, l1);
            Ahp[kp + 1][row] = pack2bf(p2, p3, l2, l3);
            Alp[kp][row]     = pack2bf_o(l0, l1);
            Alp[kp + 1][row] = pack2bf_o(l2, l3);
        }
        // stage V 16x64: vertical pack across two k-rows
        {
            int kp = tid >> 5, ng = (tid & 31) * 2;
            const float* vp = &vbase[(size_t)(k0 + 2 * kp) * HA + ng];
            float2 r0 = *(const float2*)vp;
            float2 r1 = *(const float2*)(vp + HA);
            float a0, a1, a2, a3;
            unsigned h0 = pack2bf(r0.x, r1.x, a0, a1);
            unsigned h1 = pack2bf(r0.y, r1.y, a2, a3);
            Bhp[kp][ng] = h0;     Bhp[kp][ng + 1] = h1;
            Blp[kp][ng] = pack2bf_o(a0, a1);
            Blp[kp][ng + 1] = pack2bf_o(a2, a3);
        }
        __syncthreads();
        unsigned afh[2][4], afl[2][4];
        #pragma unroll
        for (int mf = 0; mf < 2; mf++) {
            int mr = warp_m * 32 + mf * 16 + g;
            afh[mf][0] = Ahp[tq][mr];     afh[mf][1] = Ahp[tq][mr + 8];
            afh[mf][2] = Ahp[tq + 4][mr]; afh[mf][3] = Ahp[tq + 4][mr + 8];
            afl[mf][0] = Alp[tq][mr];     afl[mf][1] = Alp[tq][mr + 8];
            afl[mf][2] = Alp[tq + 4][mr]; afl[mf][3] = Alp[tq + 4][mr + 8];
        }
        #pragma unroll
        for (int nf = 0; nf < 4; nf++) {
            int nc = warp_n * 32 + nf * 8 + g;
            unsigned bh[2] = { Bhp[tq][nc], Bhp[tq + 4][nc] };
            unsigned bl[2] = { Blp[tq][nc], Blp[tq + 4][nc] };
            #pragma unroll
            for (int mf = 0; mf < 2; mf++) {
                mma_bf16(acc[mf][nf], afh[mf], bh);
                mma_bf16(acc[mf][nf], afh[mf], bl);
                mma_bf16(acc[mf][nf], afl[mf], bh);
            }
        }
        __syncthreads();
    }

    #pragma unroll
    for (int mf = 0; mf < 2; mf++) {
        int lr0 = warp_m * 32 + mf * 16 + g;
        float inv0 = rs_s[lr0].y, inv1 = rs_s[lr0 + 8].y;
        int row0 = q0 + lr0;
        #pragma unroll
        for (int nf = 0; nf < 4; nf++) {
            int col = warp_n * 32 + nf * 8 + 2 * tq;
            *(float2*)&g_ctx[(size_t)(b * TT + row0) * HA + h * AD + col] =
                make_float2(acc[mf][nf][0] * inv0, acc[mf][nf][1] * inv0);
            *(float2*)&g_ctx[(size_t)(b * TT + row0 + 8) * HA + h * AD + col] =
                make_float2(acc[mf][nf][2] * inv1, acc[mf][nf][3] * inv1);
        }
    }
}

// ---------------- launch ----------------
extern "C" void kernel_launch(void* const* d_in, const int* in_sizes, int n_in,
                              void* d_out, int out_size) {
    const float* states     = (const float*)d_in[0];
    const float* key_states = (const float*)d_in[1];
    const float* masks      = (const float*)d_in[2];
    const int*   ab32       = (const int*)d_in[3];
    const float* Wq         = (const float*)d_in[4];
    const float* Wk         = (const float*)d_in[5];
    const float* Wv         = (const float*)d_in[6];
    const float* Wout       = (const float*)d_in[7];
    const float* embs       = (const float*)d_in[8];
    const float* scal       = (const float*)d_in[9];
    float* out              = (float*)d_out;

    dim3 gemm_grid(HA / 128, BT / 128);   // (8, 64)

    // QKV projections — bf16 tensor cores (3-term split)
    bf16_gemm_kernel<<<gemm_grid, 256>>>(states,     Wq, nullptr, 0, 0, BT, HA, DD);
    bf16_gemm_kernel<<<gemm_grid, 256>>>(key_states, Wk, nullptr, 0, 1, BT, HA, DD);
    bf16_gemm_kernel<<<gemm_grid, 256>>>(key_states, Wv, nullptr, 0, 2, BT, HA, DD);

    // ksum
    ksum_kernel<<<(BT * HH + 255) / 256, 256>>>();

    // edge-bias detect + projection + deterministic scatter
    detect_kernel<<<1, 1>>>(ab32);
    proj_kernel<<<1, 32>>>(embs, scal);
    zero_bs_kernel<<<(BB * TT * TT / 4 + 255) / 256, 256>>>();
    scatter_pass1_kernel<<<(NEDGE + 255) / 256, 256>>>(ab32);
    scatter_pass2_kernel<<<(NEDGE + 255) / 256, 256>>>(ab32);

    // scores (bf16) + row stats
    dim3 sc_grid(TT / 128, TT / 128, BB * HH);   // (8, 8, 128)
    scores_bf16_kernel<<<sc_grid, 256>>>(masks);
    rowstat_kernel<<<BB * HH * TT, 256>>>();

    // context (bf16, fused exp-normalize)
    dim3 cx_grid(TT / 128, BB * HH);             // (8, 128)
    context_bf16_kernel<<<cx_grid, 256>>>();

    // output projection — bf16 tensor cores
    bf16_gemm_kernel<<<gemm_grid, 256>>>(nullptr, Wout, out, 1, 3, BT, DD, HA);
}